// round 13
// baseline (speedup 1.0000x reference)
#include <cuda_runtime.h>
#include <cuda_fp16.h>
#include <cuda_bf16.h>
#include <cstdint>

// ---------------- problem constants ----------------
constexpr int L  = 2048;
constexpr int E  = 1024;
constexpr int NH = 16;
constexpr int HD = 64;
constexpr float KSCALE = 0.04508422002778011f;   // log2(e)/32

// ---------------- device scratch (all 1-term fp16) ----------------
__device__ __half g_xq[L * E], g_xk[L * E], g_xv[L * E];
__device__ __half g_wq[E * E], g_wk[E * E], g_wv[E * E], g_wo[E * E];
__device__ __half g_pq[L * E];                  // projected Q (scaled)
__device__ __half g_pk[L * E];                  // projected K
__device__ __half g_pv[L * E];                  // projected V
__device__ __half g_cx[L * E];                  // context
__device__ __nv_bfloat16 g_biasbf[(size_t)L * L];  // bias * log2e/32, bf16

// ---------------- helpers ----------------
__device__ __forceinline__ uint32_t s2u(const void* p) {
    uint32_t a;
    asm("{ .reg .u64 t; cvta.to.shared.u64 t, %1; cvt.u32.u64 %0, t; }"
        : "=r"(a) : "l"(p));
    return a;
}
__device__ __forceinline__ uint32_t sw128(uint32_t off) {
    return off ^ ((off >> 3) & 0x70);
}
__device__ __forceinline__ float ex2f(float x) {
    float r; asm("ex2.approx.f32 %0, %1;" : "=f"(r) : "f"(x)); return r;
}
__device__ __forceinline__ uint32_t pack_h2(float lo, float hi) {
    uint32_t r;
    asm("cvt.rn.f16x2.f32 %0, %1, %2;" : "=r"(r) : "f"(hi), "f"(lo));
    return r;
}
__device__ __forceinline__ uint32_t pack_bf2(float lo, float hi) {
    uint32_t r;
    asm("cvt.rn.bf16x2.f32 %0, %1, %2;" : "=r"(r) : "f"(hi), "f"(lo));
    return r;
}

#define CP_ASYNC16(dst, src) \
    asm volatile("cp.async.cg.shared.global [%0], [%1], 16;" :: "r"(dst), "l"(src))
#define CP_COMMIT() asm volatile("cp.async.commit_group;" ::: "memory")
#define CP_WAIT1()  asm volatile("cp.async.wait_group 1;" ::: "memory")
#define CP_WAIT0()  asm volatile("cp.async.wait_group 0;" ::: "memory")

#define LDSM4(r0, r1, r2, r3, a) \
    asm volatile("ldmatrix.sync.aligned.m8n8.x4.shared.b16 {%0,%1,%2,%3}, [%4];" \
        : "=r"(r0), "=r"(r1), "=r"(r2), "=r"(r3) : "r"(a))
#define LDSM4T(r0, r1, r2, r3, a) \
    asm volatile("ldmatrix.sync.aligned.m8n8.x4.trans.shared.b16 {%0,%1,%2,%3}, [%4];" \
        : "=r"(r0), "=r"(r1), "=r"(r2), "=r"(r3) : "r"(a))

#define MMA16816(d, a, b) \
    asm volatile("mma.sync.aligned.m16n8k16.row.col.f32.f16.f16.f32 " \
        "{%0,%1,%2,%3}, {%4,%5,%6,%7}, {%8,%9}, {%0,%1,%2,%3};" \
        : "+f"((d)[0]), "+f"((d)[1]), "+f"((d)[2]), "+f"((d)[3]) \
        : "r"((a)[0]), "r"((a)[1]), "r"((a)[2]), "r"((a)[3]), \
          "r"((b)[0]), "r"((b)[1]))

// cp.async one [128 x 64] f16 tile into SW128-swizzled smem (256 threads)
__device__ __forceinline__ void cp_tile(uint32_t dst, const __half* src,
                                        int ld, int tid) {
#pragma unroll
    for (int i = 0; i < 4; i++) {
        int u   = i * 256 + tid;
        int row = u >> 3;
        int ch  = u & 7;
        uint32_t d = dst + sw128((uint32_t)(row * 128 + ch * 16));
        CP_ASYNC16(d, src + (size_t)row * ld + ch * 8);
    }
}

// cp.async one [64 x 64] f16 tile into SW128-swizzled smem (256 threads)
__device__ __forceinline__ void cp_tile64(uint32_t dst, const __half* src,
                                          int ld, int tid) {
#pragma unroll
    for (int i = 0; i < 2; i++) {
        int u   = i * 256 + tid;
        int row = u >> 3;
        int ch  = u & 7;
        uint32_t d = dst + sw128((uint32_t)(row * 128 + ch * 16));
        CP_ASYNC16(d, src + (size_t)row * ld + ch * 8);
    }
}

// ---------------- fused conversion ----------------
__device__ __forceinline__ void conv1_at(const float* s, __half* d, int i) {
    float4 v = *reinterpret_cast<const float4*>(s + i);
    uint2 o = { pack_h2(v.x, v.y), pack_h2(v.z, v.w) };
    *reinterpret_cast<uint2*>(d + i) = o;
}

constexpr int LE = L * E, EE = E * E;

__global__ void conv_all(const float* q, const float* k, const float* v,
                         const float* Wq, const float* Wk,
                         const float* Wv, const float* Wo,
                         __half* xq, __half* xk, __half* xv,
                         __half* wq, __half* wk, __half* wv, __half* wo)
{
    int i = (blockIdx.x * blockDim.x + threadIdx.x) * 4;
    if (i < LE) { conv1_at(q, xq, i); return; }
    i -= LE;
    if (i < LE) { conv1_at(k, xk, i); return; }
    i -= LE;
    if (i < LE) { conv1_at(v, xv, i); return; }
    i -= LE;
    if (i < EE) { conv1_at(Wq, wq, i); return; }
    i -= EE;
    if (i < EE) { conv1_at(Wk, wk, i); return; }
    i -= EE;
    if (i < EE) { conv1_at(Wv, wv, i); return; }
    i -= EE;
    conv1_at(Wo, wo, i);
}

// ---------------- bias table: bf16( log2e/32 * 1/(d+1) ) ----------------
__global__ void bias_prep(const float* __restrict__ d, __nv_bfloat16* __restrict__ b)
{
    int i = (blockIdx.x * blockDim.x + threadIdx.x) * 4;
    float4 v = *reinterpret_cast<const float4*>(d + i);
    float o0 = (v.x == 0.f) ? 0.f : KSCALE / (v.x + 1.f);
    float o1 = (v.y == 0.f) ? 0.f : KSCALE / (v.y + 1.f);
    float o2 = (v.z == 0.f) ? 0.f : KSCALE / (v.z + 1.f);
    float o3 = (v.w == 0.f) ? 0.f : KSCALE / (v.w + 1.f);
    uint2 o = { pack_bf2(o0, o1), pack_bf2(o2, o3) };
    *reinterpret_cast<uint2*>(b + i) = o;
}

// ---------------- 1-term GEMM core (128x128 tile, 2 CTAs/SM) ----------------
constexpr int G1_SMEM = 65536;

template <typename EPI>
__device__ __forceinline__ void gemm1_body(const __half* A, const __half* B,
                                           int m0, int n0, EPI epi)
{
    extern __shared__ char sm[];
    const uint32_t sb = s2u(sm);
    const int tid  = threadIdx.x;
    const int wid  = tid >> 5;
    const int lane = tid & 31;
    const int m0w  = (wid >> 2) * 64;
    const int n0w  = (wid & 3) * 32;
    const int sub = lane >> 3, lr = lane & 7;
    const int K = E;

    float acc[4][4][4];
#pragma unroll
    for (int i = 0; i < 4; i++)
#pragma unroll
        for (int j = 0; j < 4; j++)
#pragma unroll
            for (int k = 0; k < 4; k++) acc[i][j][k] = 0.f;

    const int NC = K / 64;
    cp_tile(sb,         A + (size_t)m0 * K, K, tid);
    cp_tile(sb + 16384, B + (size_t)n0 * K, K, tid);
    CP_COMMIT();

    for (int kc = 0; kc < NC; kc++) {
        if (kc + 1 < NC) {
            uint32_t base = sb + ((kc + 1) & 1) * 32768;
            const int k0 = (kc + 1) * 64;
            cp_tile(base,         A + (size_t)m0 * K + k0, K, tid);
            cp_tile(base + 16384, B + (size_t)n0 * K + k0, K, tid);
            CP_COMMIT();
            CP_WAIT1();
        } else {
            CP_WAIT0();
        }
        __syncthreads();

        const uint32_t base = sb + (kc & 1) * 32768;
#pragma unroll
        for (int ks = 0; ks < 4; ks++) {
            const int ch = ks * 2 + (sub >> 1);
            uint32_t ah[4][4], bh[4][2];
#pragma unroll
            for (int mi = 0; mi < 4; mi++) {
                int r = m0w + mi * 16 + (sub & 1) * 8 + lr;
                uint32_t off = sw128((uint32_t)(r * 128 + ch * 16));
                LDSM4(ah[mi][0], ah[mi][1], ah[mi][2], ah[mi][3], base + off);
            }
#pragma unroll
            for (int ng = 0; ng < 2; ng++) {
                int r = n0w + ng * 16 + (sub & 1) * 8 + lr;
                uint32_t off = sw128((uint32_t)(r * 128 + ch * 16));
                uint32_t t0, t1, t2, t3;
                LDSM4(t0, t1, t2, t3, base + 16384 + off);
                bh[2*ng][0] = t0; bh[2*ng][1] = t2;
                bh[2*ng+1][0] = t1; bh[2*ng+1][1] = t3;
            }
#pragma unroll
            for (int mi = 0; mi < 4; mi++)
#pragma unroll
                for (int ni = 0; ni < 4; ni++)
                    MMA16816(acc[mi][ni], ah[mi], bh[ni]);
        }
        __syncthreads();
    }

#pragma unroll
    for (int mi = 0; mi < 4; mi++) {
        int r1 = m0 + m0w + mi * 16 + (lane >> 2);
#pragma unroll
        for (int ni = 0; ni < 4; ni++) {
            int col = n0 + n0w + ni * 8 + (lane & 3) * 2;
            epi(acc[mi][ni], r1, col);
        }
    }
}

__global__ void __launch_bounds__(256, 2)
gemm1_qkv(const __half* __restrict__ xq, const __half* __restrict__ wq,
          __half* __restrict__ pq,
          const __half* __restrict__ xk, const __half* __restrict__ wk,
          __half* __restrict__ pk,
          const __half* __restrict__ xv, const __half* __restrict__ wv,
          __half* __restrict__ pv)
{
    const __half* A = (blockIdx.z == 0) ? xq : (blockIdx.z == 1) ? xk : xv;
    const __half* B = (blockIdx.z == 0) ? wq : (blockIdx.z == 1) ? wk : wv;
    __half* C       = (blockIdx.z == 0) ? pq : (blockIdx.z == 1) ? pk : pv;
    const float oscale = (blockIdx.z == 0) ? KSCALE : 1.0f;
    const int m0 = blockIdx.y * 128, n0 = blockIdx.x * 128;

    gemm1_body(A, B, m0, n0,
        [&](float* d, int r1, int col) {
            *reinterpret_cast<uint32_t*>(C + (size_t)r1 * E + col) =
                pack_h2(d[0] * oscale, d[1] * oscale);
            *reinterpret_cast<uint32_t*>(C + (size_t)(r1 + 8) * E + col) =
                pack_h2(d[2] * oscale, d[3] * oscale);
        });
}

__global__ void __launch_bounds__(256, 2)
gemm1_o(const __half* __restrict__ cx, const __half* __restrict__ wo,
        float* __restrict__ out, const float* __restrict__ bvec)
{
    const int m0 = blockIdx.y * 128, n0 = blockIdx.x * 128;
    gemm1_body(cx, wo, m0, n0,
        [&](float* d, int r1, int col) {
            float2 bv = *reinterpret_cast<const float2*>(bvec + col);
            float2 o1 = {d[0] + bv.x, d[1] + bv.y};
            float2 o2 = {d[2] + bv.x, d[3] + bv.y};
            *reinterpret_cast<float2*>(out + (size_t)r1 * E + col) = o1;
            *reinterpret_cast<float2*>(out + (size_t)(r1 + 8) * E + col) = o2;
        });
}

// ---------------- attention: register P, 64q CTA, 32q x 32k warps ----------
// CTA = 64 q x 1 head, 256 threads, 2 CTAs/SM.
//   mg = wid>>2 (0..1): rows mg*32..+31 (2 sub-tiles of 16)
//   ng = wid&3  (0..3): keys ng*32..+31 of the 128-key tile
// K/V fragments feed 2 MMAs each (halved LDSM vs 16q x 64k tiling).
// 4-way O/lsum reduction once at the end, in reused KV smem.
// smem: Q(8K) | stage0 K,V(32K) | stage1(32K) = 72KB.
constexpr uint32_t AQ   = 0;
constexpr uint32_t AKV0 = 8192;
constexpr uint32_t AKV1 = 40960;
constexpr int ATTN_SMEM = 73728;

__global__ void __launch_bounds__(256, 2)
attn_tc(const __half* __restrict__ Q,
        const __half* __restrict__ Kp,
        const __half* __restrict__ Vp,
        const __nv_bfloat16* __restrict__ biasbf,
        __half* __restrict__ Cx)
{
    extern __shared__ char sm[];
    const uint32_t sb = s2u(sm);
    const int tid  = threadIdx.x;
    const int wid  = tid >> 5;
    const int lane = tid & 31;
    const int mg   = wid >> 2;          // 0..1
    const int ng   = wid & 3;           // 0..3
    const int m0w  = mg * 32;
    const int kbase = ng * 32;
    const int q0   = blockIdx.x * 64;
    const int hoff = blockIdx.y * HD;
    const int sub = lane >> 3, lr = lane & 7;

    // prologue: Q group, then KV0 group
    cp_tile64(sb + AQ, Q + (size_t)q0 * E + hoff, E, tid);
    CP_COMMIT();
    cp_tile(sb + AKV0,         Kp + hoff, E, tid);
    cp_tile(sb + AKV0 + 16384, Vp + hoff, E, tid);
    CP_COMMIT();
    CP_WAIT1();            // Q group done
    __syncthreads();

    float acc_o[2][8][4];          // 32 rows x 64 d-cols (partial over keys)
#pragma unroll
    for (int i = 0; i < 2; i++)
#pragma unroll
        for (int j = 0; j < 8; j++)
#pragma unroll
            for (int k = 0; k < 4; k++) acc_o[i][j][k] = 0.f;
    float lsum[2][2];
    lsum[0][0] = lsum[0][1] = lsum[1][0] = lsum[1][1] = 0.f;

    for (int kt = 0; kt < L / 128; kt++) {
        const int kb = kt * 128;
        if (kt + 1 < L / 128) {
            uint32_t base = sb + (((kt + 1) & 1) ? AKV1 : AKV0);
            const size_t ro = (size_t)(kb + 128) * E + hoff;
            cp_tile(base,         Kp + ro, E, tid);
            cp_tile(base + 16384, Vp + ro, E, tid);
            CP_COMMIT();
            CP_WAIT1();
        } else {
            CP_WAIT0();
        }
        __syncthreads();

        const uint32_t bkv = sb + ((kt & 1) ? AKV1 : AKV0);

        // ---- S = Q @ K^T over this warp's 32 keys ----
        float acc_s[2][4][4];
#pragma unroll
        for (int i = 0; i < 2; i++)
#pragma unroll
            for (int j = 0; j < 4; j++)
#pragma unroll
                for (int k = 0; k < 4; k++) acc_s[i][j][k] = 0.f;

#pragma unroll
        for (int ks = 0; ks < 4; ks++) {
            const int ch = ks * 2 + (sub >> 1);
            uint32_t qa[2][4], bh[4][2];
#pragma unroll
            for (int mi = 0; mi < 2; mi++) {
                int r = m0w + mi * 16 + (sub & 1) * 8 + lr;
                uint32_t off = sw128((uint32_t)(r * 128 + ch * 16));
                LDSM4(qa[mi][0], qa[mi][1], qa[mi][2], qa[mi][3], sb + AQ + off);
            }
#pragma unroll
            for (int kg = 0; kg < 2; kg++) {
                int r = kbase + kg * 16 + (sub & 1) * 8 + lr;
                uint32_t off = sw128((uint32_t)(r * 128 + ch * 16));
                uint32_t t0, t1, t2, t3;
                LDSM4(t0, t1, t2, t3, bkv + off);
                bh[2*kg][0] = t0; bh[2*kg][1] = t2;
                bh[2*kg+1][0] = t1; bh[2*kg+1][1] = t3;
            }
#pragma unroll
            for (int mi = 0; mi < 2; mi++)
#pragma unroll
                for (int n = 0; n < 4; n++)
                    MMA16816(acc_s[mi][n], qa[mi], bh[n]);
        }

        // ---- p = ex2(S + bias) in registers; pack to PV A-fragments ----
        uint32_t pf[2][2][4];
#pragma unroll
        for (int mi = 0; mi < 2; mi++) {
            const int lr1 = m0w + mi * 16 + (lane >> 2);
            const int lr2 = lr1 + 8;
            const uint32_t* bp1 = reinterpret_cast<const uint32_t*>(
                biasbf + (size_t)(q0 + lr1) * L + kb + kbase);
            const uint32_t* bp2 = reinterpret_cast<const uint32_t*>(
                biasbf + (size_t)(q0 + lr2) * L + kb + kbase);
#pragma unroll
            for (int n = 0; n < 4; n++) {
                const int lc = n * 8 + (lane & 3) * 2;
                uint32_t pk1 = bp1[lc >> 1];
                uint32_t pk2 = bp2[lc >> 1];
                float* d = acc_s[mi][n];
                float p0 = ex2f(d[0] + __uint_as_float(pk1 << 16));
                float p1 = ex2f(d[1] + __uint_as_float(pk1 & 0xffff0000u));
                float p2 = ex2f(d[2] + __uint_as_float(pk2 << 16));
                float p3 = ex2f(d[3] + __uint_as_float(pk2 & 0xffff0000u));
                lsum[mi][0] += p0 + p1;
                lsum[mi][1] += p2 + p3;
                const int t = n >> 1, j = n & 1;
                pf[mi][t][2*j]     = pack_h2(p0, p1);   // rows r   (a0/a2)
                pf[mi][t][2*j + 1] = pack_h2(p2, p3);   // rows r+8 (a1/a3)
            }
        }

        // ---- O += P @ V (registers -> MMA, V via LDSM4T) ----
#pragma unroll
        for (int t = 0; t < 2; t++) {
            int rv = kbase + t * 16 + (sub >> 1) * 8 + lr;
#pragma unroll
            for (int dn = 0; dn < 4; dn++) {
                int cv = dn * 2 + (sub & 1);
                uint32_t off = sw128((uint32_t)(rv * 128 + cv * 16));
                uint32_t t0, t1, t2, t3;
                LDSM4T(t0, t1, t2, t3, bkv + 16384 + off);
                uint32_t b0[2] = {t0, t2}, b1[2] = {t1, t3};
#pragma unroll
                for (int mi = 0; mi < 2; mi++) {
                    MMA16816(acc_o[mi][2*dn],     pf[mi][t], b0);
                    MMA16816(acc_o[mi][2*dn + 1], pf[mi][t], b1);
                }
            }
        }
        __syncthreads();
    }

    // ---- 4-way reduction across ng groups (reuse KV smem) ----
    float* obuf = reinterpret_cast<float*>(sm + AKV0);            // 48KB used
    float* sbuf = reinterpret_cast<float*>(sm + AKV0 + 49152);    // 4*64 floats

#pragma unroll
    for (int mi = 0; mi < 2; mi++)
#pragma unroll
        for (int h = 0; h < 2; h++) {
            float v = lsum[mi][h];
            v += __shfl_xor_sync(0xffffffffu, v, 1);
            v += __shfl_xor_sync(0xffffffffu, v, 2);
            if ((lane & 3) == 0) {
                int row = m0w + mi * 16 + h * 8 + (lane >> 2);
                sbuf[ng * 64 + row] = v;
            }
        }

    if (ng != 0) {
        float* dst = obuf + (size_t)(ng - 1) * 64 * 64;
#pragma unroll
        for (int mi = 0; mi < 2; mi++) {
            const int lr1 = m0w + mi * 16 + (lane >> 2);
            const int lr2 = lr1 + 8;
#pragma unroll
            for (int n = 0; n < 8; n++) {
                const int col = n * 8 + (lane & 3) * 2;
                float* d = acc_o[mi][n];
                float2 v1 = {d[0], d[1]}, v2 = {d[2], d[3]};
                *reinterpret_cast<float2*>(&dst[lr1 * 64 + col]) = v1;
                *reinterpret_cast<float2*>(&dst[lr2 * 64 + col]) = v2;
            }
        }
    }
    __syncthreads();

    if (ng == 0) {
#pragma unroll
        for (int mi = 0; mi < 2; mi++) {
            const int lr1 = m0w + mi * 16 + (lane >> 2);
            const int lr2 = lr1 + 8;
            const float i1 = 1.0f / (sbuf[lr1] + sbuf[64 + lr1] +
                                     sbuf[128 + lr1] + sbuf[192 + lr1]);
            const float i2 = 1.0f / (sbuf[lr2] + sbuf[64 + lr2] +
                                     sbuf[128 + lr2] + sbuf[192 + lr2]);
#pragma unroll
            for (int n = 0; n < 8; n++) {
                const int col = n * 8 + (lane & 3) * 2;
                float* d = acc_o[mi][n];
                float2 a1 = *reinterpret_cast<float2*>(&obuf[lr1 * 64 + col]);
                float2 b1 = *reinterpret_cast<float2*>(&obuf[4096 + lr1 * 64 + col]);
                float2 c1 = *reinterpret_cast<float2*>(&obuf[8192 + lr1 * 64 + col]);
                float2 a2 = *reinterpret_cast<float2*>(&obuf[lr2 * 64 + col]);
                float2 b2 = *reinterpret_cast<float2*>(&obuf[4096 + lr2 * 64 + col]);
                float2 c2 = *reinterpret_cast<float2*>(&obuf[8192 + lr2 * 64 + col]);
                size_t idx = (size_t)(q0 + lr1) * E + hoff + col;
                *reinterpret_cast<uint32_t*>(Cx + idx) =
                    pack_h2((d[0] + a1.x + b1.x + c1.x) * i1,
                            (d[1] + a1.y + b1.y + c1.y) * i1);
                idx = (size_t)(q0 + lr2) * E + hoff + col;
                *reinterpret_cast<uint32_t*>(Cx + idx) =
                    pack_h2((d[2] + a2.x + b2.x + c2.x) * i2,
                            (d[3] + a2.y + b2.y + c2.y) * i2);
            }
        }
    }
}

// ---------------- host side ----------------
extern "C" void kernel_launch(void* const* d_in, const int* in_sizes, int n_in,
                              void* d_out, int out_size)
{
    const float* values = (const float*)d_in[0];
    const float* keys   = (const float*)d_in[1];
    const float* query  = (const float*)d_in[2];
    const float* dist   = (const float*)d_in[3];
    const float* Wv     = (const float*)d_in[4];
    const float* Wk     = (const float*)d_in[5];
    const float* Wq     = (const float*)d_in[6];
    const float* Wo     = (const float*)d_in[7];
    const float* bo     = (const float*)d_in[8];
    float* out = (float*)d_out;

    __half *xq, *xk, *xv, *wq, *wk, *wv, *wo;
    __half *pq, *pk, *pv, *cx;
    __nv_bfloat16* biasbf;
    cudaGetSymbolAddress((void**)&xq, g_xq);
    cudaGetSymbolAddress((void**)&xk, g_xk);
    cudaGetSymbolAddress((void**)&xv, g_xv);
    cudaGetSymbolAddress((void**)&wq, g_wq);
    cudaGetSymbolAddress((void**)&wk, g_wk);
    cudaGetSymbolAddress((void**)&wv, g_wv);
    cudaGetSymbolAddress((void**)&wo, g_wo);
    cudaGetSymbolAddress((void**)&pq, g_pq);
    cudaGetSymbolAddress((void**)&pk, g_pk);
    cudaGetSymbolAddress((void**)&pv, g_pv);
    cudaGetSymbolAddress((void**)&cx, g_cx);
    cudaGetSymbolAddress((void**)&biasbf, g_biasbf);

    cudaFuncSetAttribute(gemm1_qkv, cudaFuncAttributeMaxDynamicSharedMemorySize, G1_SMEM);
    cudaFuncSetAttribute(gemm1_o,   cudaFuncAttributeMaxDynamicSharedMemorySize, G1_SMEM);
    cudaFuncSetAttribute(attn_tc,   cudaFuncAttributeMaxDynamicSharedMemorySize, ATTN_SMEM);

    // launches: 1 conv, 2 bias, 3 qkv, 4 attn, 5 o
    const int nConv = (3 * LE + 4 * EE) / 4 / 256;
    conv_all<<<nConv, 256>>>(query, keys, values, Wq, Wk, Wv, Wo,
                             xq, xk, xv, wq, wk, wv, wo);
    bias_prep<<<(L * L) / 4 / 256, 256>>>(dist, biasbf);

    dim3 gqkv(E / 128, L / 128, 3);   // 384 CTAs
    gemm1_qkv<<<gqkv, 256, G1_SMEM>>>(xq, wq, pq, xk, wk, pk, xv, wv, pv);

    attn_tc<<<dim3(L / 64, NH), 256, ATTN_SMEM>>>(pq, pk, pv, biasbf, cx);

    dim3 go(E / 128, L / 128);        // 128 CTAs
    gemm1_o<<<go, 256, G1_SMEM>>>(cx, wo, out, bo);
}

// round 14
// speedup vs baseline: 1.1223x; 1.1223x over previous
#include <cuda_runtime.h>
#include <cuda_fp16.h>
#include <cuda_bf16.h>
#include <cstdint>

// ---------------- problem constants ----------------
constexpr int L  = 2048;
constexpr int E  = 1024;
constexpr int NH = 16;
constexpr int HD = 64;
constexpr float KSCALE = 0.04508422002778011f;   // log2(e)/32

// ---------------- device scratch (all 1-term fp16) ----------------
__device__ __half g_xq[L * E], g_xk[L * E], g_xv[L * E];
__device__ __half g_wq[E * E], g_wk[E * E], g_wv[E * E], g_wo[E * E];
__device__ __half g_pq[L * E];                  // projected Q (scaled)
__device__ __half g_pk[L * E];                  // projected K
__device__ __half g_pv[L * E];                  // projected V
__device__ __half g_cx[L * E];                  // context
__device__ __nv_bfloat16 g_biasbf[(size_t)L * L];  // bias * log2e/32, bf16

// ---------------- helpers ----------------
__device__ __forceinline__ uint32_t s2u(const void* p) {
    uint32_t a;
    asm("{ .reg .u64 t; cvta.to.shared.u64 t, %1; cvt.u32.u64 %0, t; }"
        : "=r"(a) : "l"(p));
    return a;
}
__device__ __forceinline__ uint32_t sw128(uint32_t off) {
    return off ^ ((off >> 3) & 0x70);
}
__device__ __forceinline__ float ex2f(float x) {
    float r; asm("ex2.approx.f32 %0, %1;" : "=f"(r) : "f"(x)); return r;
}
__device__ __forceinline__ uint32_t pack_h2(float lo, float hi) {
    uint32_t r;
    asm("cvt.rn.f16x2.f32 %0, %1, %2;" : "=r"(r) : "f"(hi), "f"(lo));
    return r;
}
__device__ __forceinline__ uint32_t pack_bf2(float lo, float hi) {
    uint32_t r;
    asm("cvt.rn.bf16x2.f32 %0, %1, %2;" : "=r"(r) : "f"(hi), "f"(lo));
    return r;
}

#define CP_ASYNC16(dst, src) \
    asm volatile("cp.async.cg.shared.global [%0], [%1], 16;" :: "r"(dst), "l"(src))
#define CP_COMMIT() asm volatile("cp.async.commit_group;" ::: "memory")
#define CP_WAIT1()  asm volatile("cp.async.wait_group 1;" ::: "memory")
#define CP_WAIT0()  asm volatile("cp.async.wait_group 0;" ::: "memory")

#define LDSM4(r0, r1, r2, r3, a) \
    asm volatile("ldmatrix.sync.aligned.m8n8.x4.shared.b16 {%0,%1,%2,%3}, [%4];" \
        : "=r"(r0), "=r"(r1), "=r"(r2), "=r"(r3) : "r"(a))
#define LDSM4T(r0, r1, r2, r3, a) \
    asm volatile("ldmatrix.sync.aligned.m8n8.x4.trans.shared.b16 {%0,%1,%2,%3}, [%4];" \
        : "=r"(r0), "=r"(r1), "=r"(r2), "=r"(r3) : "r"(a))

#define MMA16816(d, a, b) \
    asm volatile("mma.sync.aligned.m16n8k16.row.col.f32.f16.f16.f32 " \
        "{%0,%1,%2,%3}, {%4,%5,%6,%7}, {%8,%9}, {%0,%1,%2,%3};" \
        : "+f"((d)[0]), "+f"((d)[1]), "+f"((d)[2]), "+f"((d)[3]) \
        : "r"((a)[0]), "r"((a)[1]), "r"((a)[2]), "r"((a)[3]), \
          "r"((b)[0]), "r"((b)[1]))

// cp.async one [128 x 64] f16 tile into SW128-swizzled smem (256 threads)
__device__ __forceinline__ void cp_tile(uint32_t dst, const __half* src,
                                        int ld, int tid) {
#pragma unroll
    for (int i = 0; i < 4; i++) {
        int u   = i * 256 + tid;
        int row = u >> 3;
        int ch  = u & 7;
        uint32_t d = dst + sw128((uint32_t)(row * 128 + ch * 16));
        CP_ASYNC16(d, src + (size_t)row * ld + ch * 8);
    }
}

// cp.async one [128 x 64] f16 tile, 128 threads
__device__ __forceinline__ void cp_tile_h(uint32_t dst, const __half* src,
                                          int ld, int tid) {
#pragma unroll
    for (int i = 0; i < 8; i++) {
        int u   = i * 128 + tid;
        int row = u >> 3;
        int ch  = u & 7;
        uint32_t d = dst + sw128((uint32_t)(row * 128 + ch * 16));
        CP_ASYNC16(d, src + (size_t)row * ld + ch * 8);
    }
}

// cp.async one [64 x 64] f16 tile, 128 threads
__device__ __forceinline__ void cp_tile_q(uint32_t dst, const __half* src,
                                          int ld, int tid) {
#pragma unroll
    for (int i = 0; i < 4; i++) {
        int u   = i * 128 + tid;
        int row = u >> 3;
        int ch  = u & 7;
        uint32_t d = dst + sw128((uint32_t)(row * 128 + ch * 16));
        CP_ASYNC16(d, src + (size_t)row * ld + ch * 8);
    }
}

// ---------------- fused conversion ----------------
__device__ __forceinline__ void conv1_at(const float* s, __half* d, int i) {
    float4 v = *reinterpret_cast<const float4*>(s + i);
    uint2 o = { pack_h2(v.x, v.y), pack_h2(v.z, v.w) };
    *reinterpret_cast<uint2*>(d + i) = o;
}

constexpr int LE = L * E, EE = E * E;

__global__ void conv_all(const float* q, const float* k, const float* v,
                         const float* Wq, const float* Wk,
                         const float* Wv, const float* Wo,
                         __half* xq, __half* xk, __half* xv,
                         __half* wq, __half* wk, __half* wv, __half* wo)
{
    int i = (blockIdx.x * blockDim.x + threadIdx.x) * 4;
    if (i < LE) { conv1_at(q, xq, i); return; }
    i -= LE;
    if (i < LE) { conv1_at(k, xk, i); return; }
    i -= LE;
    if (i < LE) { conv1_at(v, xv, i); return; }
    i -= LE;
    if (i < EE) { conv1_at(Wq, wq, i); return; }
    i -= EE;
    if (i < EE) { conv1_at(Wk, wk, i); return; }
    i -= EE;
    if (i < EE) { conv1_at(Wv, wv, i); return; }
    i -= EE;
    conv1_at(Wo, wo, i);
}

// ---------------- bias table: bf16( log2e/32 * 1/(d+1) ) ----------------
__global__ void bias_prep(const float* __restrict__ d, __nv_bfloat16* __restrict__ b)
{
    int i = (blockIdx.x * blockDim.x + threadIdx.x) * 4;
    float4 v = *reinterpret_cast<const float4*>(d + i);
    float o0 = (v.x == 0.f) ? 0.f : KSCALE / (v.x + 1.f);
    float o1 = (v.y == 0.f) ? 0.f : KSCALE / (v.y + 1.f);
    float o2 = (v.z == 0.f) ? 0.f : KSCALE / (v.z + 1.f);
    float o3 = (v.w == 0.f) ? 0.f : KSCALE / (v.w + 1.f);
    uint2 o = { pack_bf2(o0, o1), pack_bf2(o2, o3) };
    *reinterpret_cast<uint2*>(b + i) = o;
}

// ---------------- 1-term GEMM core (128x128 tile, 2 CTAs/SM) ----------------
constexpr int G1_SMEM = 65536;

template <typename EPI>
__device__ __forceinline__ void gemm1_body(const __half* A, const __half* B,
                                           int m0, int n0, EPI epi)
{
    extern __shared__ char sm[];
    const uint32_t sb = s2u(sm);
    const int tid  = threadIdx.x;
    const int wid  = tid >> 5;
    const int lane = tid & 31;
    const int m0w  = (wid >> 2) * 64;
    const int n0w  = (wid & 3) * 32;
    const int sub = lane >> 3, lr = lane & 7;
    const int K = E;

    float acc[4][4][4];
#pragma unroll
    for (int i = 0; i < 4; i++)
#pragma unroll
        for (int j = 0; j < 4; j++)
#pragma unroll
            for (int k = 0; k < 4; k++) acc[i][j][k] = 0.f;

    const int NC = K / 64;
    cp_tile(sb,         A + (size_t)m0 * K, K, tid);
    cp_tile(sb + 16384, B + (size_t)n0 * K, K, tid);
    CP_COMMIT();

    for (int kc = 0; kc < NC; kc++) {
        if (kc + 1 < NC) {
            uint32_t base = sb + ((kc + 1) & 1) * 32768;
            const int k0 = (kc + 1) * 64;
            cp_tile(base,         A + (size_t)m0 * K + k0, K, tid);
            cp_tile(base + 16384, B + (size_t)n0 * K + k0, K, tid);
            CP_COMMIT();
            CP_WAIT1();
        } else {
            CP_WAIT0();
        }
        __syncthreads();

        const uint32_t base = sb + (kc & 1) * 32768;
#pragma unroll
        for (int ks = 0; ks < 4; ks++) {
            const int ch = ks * 2 + (sub >> 1);
            uint32_t ah[4][4], bh[4][2];
#pragma unroll
            for (int mi = 0; mi < 4; mi++) {
                int r = m0w + mi * 16 + (sub & 1) * 8 + lr;
                uint32_t off = sw128((uint32_t)(r * 128 + ch * 16));
                LDSM4(ah[mi][0], ah[mi][1], ah[mi][2], ah[mi][3], base + off);
            }
#pragma unroll
            for (int ng = 0; ng < 2; ng++) {
                int r = n0w + ng * 16 + (sub & 1) * 8 + lr;
                uint32_t off = sw128((uint32_t)(r * 128 + ch * 16));
                uint32_t t0, t1, t2, t3;
                LDSM4(t0, t1, t2, t3, base + 16384 + off);
                bh[2*ng][0] = t0; bh[2*ng][1] = t2;
                bh[2*ng+1][0] = t1; bh[2*ng+1][1] = t3;
            }
#pragma unroll
            for (int mi = 0; mi < 4; mi++)
#pragma unroll
                for (int ni = 0; ni < 4; ni++)
                    MMA16816(acc[mi][ni], ah[mi], bh[ni]);
        }
        __syncthreads();
    }

#pragma unroll
    for (int mi = 0; mi < 4; mi++) {
        int r1 = m0 + m0w + mi * 16 + (lane >> 2);
#pragma unroll
        for (int ni = 0; ni < 4; ni++) {
            int col = n0 + n0w + ni * 8 + (lane & 3) * 2;
            epi(acc[mi][ni], r1, col);
        }
    }
}

__global__ void __launch_bounds__(256, 2)
gemm1_qkv(const __half* __restrict__ xq, const __half* __restrict__ wq,
          __half* __restrict__ pq,
          const __half* __restrict__ xk, const __half* __restrict__ wk,
          __half* __restrict__ pk,
          const __half* __restrict__ xv, const __half* __restrict__ wv,
          __half* __restrict__ pv)
{
    const __half* A = (blockIdx.z == 0) ? xq : (blockIdx.z == 1) ? xk : xv;
    const __half* B = (blockIdx.z == 0) ? wq : (blockIdx.z == 1) ? wk : wv;
    __half* C       = (blockIdx.z == 0) ? pq : (blockIdx.z == 1) ? pk : pv;
    const float oscale = (blockIdx.z == 0) ? KSCALE : 1.0f;
    const int m0 = blockIdx.y * 128, n0 = blockIdx.x * 128;

    gemm1_body(A, B, m0, n0,
        [&](float* d, int r1, int col) {
            *reinterpret_cast<uint32_t*>(C + (size_t)r1 * E + col) =
                pack_h2(d[0] * oscale, d[1] * oscale);
            *reinterpret_cast<uint32_t*>(C + (size_t)(r1 + 8) * E + col) =
                pack_h2(d[2] * oscale, d[3] * oscale);
        });
}

__global__ void __launch_bounds__(256, 2)
gemm1_o(const __half* __restrict__ cx, const __half* __restrict__ wo,
        float* __restrict__ out, const float* __restrict__ bvec)
{
    const int m0 = blockIdx.y * 128, n0 = blockIdx.x * 128;
    gemm1_body(cx, wo, m0, n0,
        [&](float* d, int r1, int col) {
            float2 bv = *reinterpret_cast<const float2*>(bvec + col);
            float2 o1 = {d[0] + bv.x, d[1] + bv.y};
            float2 o2 = {d[2] + bv.x, d[3] + bv.y};
            *reinterpret_cast<float2*>(out + (size_t)r1 * E + col) = o1;
            *reinterpret_cast<float2*>(out + (size_t)(r1 + 8) * E + col) = o2;
        });
}

// ---------------- attention: register P, 64q CTA, 128 threads, 2 CTAs/SM ----
// 4 warps: mg = wid>>1 (rows mg*32..+31), ng = wid&1 (keys ng*64..+63).
// R11's ratio-4 warp tile (32q x 64k, Q hoisted, register P) in a half-size
// CTA so two independent CTAs co-reside and overlap each other's bubbles.
// smem: Q(8K) | stage0 K,V(32K) | stage1(32K) = 72KB.
constexpr uint32_t AQ   = 0;
constexpr uint32_t AKV0 = 8192;
constexpr uint32_t AKV1 = 40960;
constexpr int ATTN_SMEM = 73728;

__global__ void __launch_bounds__(128, 2)
attn_tc(const __half* __restrict__ Q,
        const __half* __restrict__ Kp,
        const __half* __restrict__ Vp,
        const __nv_bfloat16* __restrict__ biasbf,
        __half* __restrict__ Cx)
{
    extern __shared__ char sm[];
    const uint32_t sb = s2u(sm);
    const int tid  = threadIdx.x;
    const int wid  = tid >> 5;
    const int lane = tid & 31;
    const int mg   = wid >> 1;          // 0..1, rows mg*32
    const int ng   = wid & 1;           // 0..1, keys ng*64
    const int m0w  = mg * 32;
    const int kbase = ng * 64;
    const int q0   = blockIdx.x * 64;
    const int hoff = blockIdx.y * HD;
    const int sub = lane >> 3, lr = lane & 7;

    // prologue: Q group, then KV0 group
    cp_tile_q(sb + AQ, Q + (size_t)q0 * E + hoff, E, tid);
    CP_COMMIT();
    cp_tile_h(sb + AKV0,         Kp + hoff, E, tid);
    cp_tile_h(sb + AKV0 + 16384, Vp + hoff, E, tid);
    CP_COMMIT();
    CP_WAIT1();            // Q group done
    __syncthreads();

    // Q fragments in registers: [ks][mi][4], rows m0w + mi*16
    uint32_t qf[4][2][4];
#pragma unroll
    for (int ks = 0; ks < 4; ks++) {
        const int ch = ks * 2 + (sub >> 1);
#pragma unroll
        for (int mi = 0; mi < 2; mi++) {
            int r = m0w + mi * 16 + (sub & 1) * 8 + lr;
            uint32_t off = sw128((uint32_t)(r * 128 + ch * 16));
            LDSM4(qf[ks][mi][0], qf[ks][mi][1], qf[ks][mi][2], qf[ks][mi][3],
                  sb + AQ + off);
        }
    }

    float acc_o[2][8][4];          // 32 rows x 64 d-cols (partial over keys)
#pragma unroll
    for (int i = 0; i < 2; i++)
#pragma unroll
        for (int j = 0; j < 8; j++)
#pragma unroll
            for (int k = 0; k < 4; k++) acc_o[i][j][k] = 0.f;
    float lsum[2][2];
    lsum[0][0] = lsum[0][1] = lsum[1][0] = lsum[1][1] = 0.f;

    for (int kt = 0; kt < L / 128; kt++) {
        const int kb = kt * 128;
        if (kt + 1 < L / 128) {
            uint32_t base = sb + (((kt + 1) & 1) ? AKV1 : AKV0);
            const size_t ro = (size_t)(kb + 128) * E + hoff;
            cp_tile_h(base,         Kp + ro, E, tid);
            cp_tile_h(base + 16384, Vp + ro, E, tid);
            CP_COMMIT();
            CP_WAIT1();
        } else {
            CP_WAIT0();
        }
        __syncthreads();

        const uint32_t bkv = sb + ((kt & 1) ? AKV1 : AKV0);

        // ---- S = Q @ K^T over this warp's 64 keys ----
        float acc_s[2][8][4];
#pragma unroll
        for (int i = 0; i < 2; i++)
#pragma unroll
            for (int j = 0; j < 8; j++)
#pragma unroll
                for (int k = 0; k < 4; k++) acc_s[i][j][k] = 0.f;

#pragma unroll
        for (int ks = 0; ks < 4; ks++) {
            const int ch = ks * 2 + (sub >> 1);
            uint32_t bh[8][2];
#pragma unroll
            for (int kg = 0; kg < 4; kg++) {
                int r = kbase + kg * 16 + (sub & 1) * 8 + lr;
                uint32_t off = sw128((uint32_t)(r * 128 + ch * 16));
                uint32_t t0, t1, t2, t3;
                LDSM4(t0, t1, t2, t3, bkv + off);
                bh[2*kg][0] = t0; bh[2*kg][1] = t2;
                bh[2*kg+1][0] = t1; bh[2*kg+1][1] = t3;
            }
#pragma unroll
            for (int mi = 0; mi < 2; mi++)
#pragma unroll
                for (int n = 0; n < 8; n++)
                    MMA16816(acc_s[mi][n], qf[ks][mi], bh[n]);
        }

        // ---- p = ex2(S + bias) in registers; pack to PV A-fragments ----
        uint32_t pf[2][4][4];
#pragma unroll
        for (int mi = 0; mi < 2; mi++) {
            const int lr1 = m0w + mi * 16 + (lane >> 2);
            const int lr2 = lr1 + 8;
            const uint32_t* bp1 = reinterpret_cast<const uint32_t*>(
                biasbf + (size_t)(q0 + lr1) * L + kb + kbase);
            const uint32_t* bp2 = reinterpret_cast<const uint32_t*>(
                biasbf + (size_t)(q0 + lr2) * L + kb + kbase);
#pragma unroll
            for (int n = 0; n < 8; n++) {
                const int lc = n * 8 + (lane & 3) * 2;
                uint32_t pk1 = bp1[lc >> 1];
                uint32_t pk2 = bp2[lc >> 1];
                float* d = acc_s[mi][n];
                float p0 = ex2f(d[0] + __uint_as_float(pk1 << 16));
                float p1 = ex2f(d[1] + __uint_as_float(pk1 & 0xffff0000u));
                float p2 = ex2f(d[2] + __uint_as_float(pk2 << 16));
                float p3 = ex2f(d[3] + __uint_as_float(pk2 & 0xffff0000u));
                lsum[mi][0] += p0 + p1;
                lsum[mi][1] += p2 + p3;
                const int t = n >> 1, j = n & 1;
                pf[mi][t][2*j]     = pack_h2(p0, p1);   // rows r   (a0/a2)
                pf[mi][t][2*j + 1] = pack_h2(p2, p3);   // rows r+8 (a1/a3)
            }
        }

        // ---- O += P @ V (registers -> MMA, V via LDSM4T) ----
#pragma unroll
        for (int t = 0; t < 4; t++) {
            int rv = kbase + t * 16 + (sub >> 1) * 8 + lr;
#pragma unroll
            for (int dn = 0; dn < 4; dn++) {
                int cv = dn * 2 + (sub & 1);
                uint32_t off = sw128((uint32_t)(rv * 128 + cv * 16));
                uint32_t t0, t1, t2, t3;
                LDSM4T(t0, t1, t2, t3, bkv + 16384 + off);
                uint32_t b0[2] = {t0, t2}, b1[2] = {t1, t3};
#pragma unroll
                for (int mi = 0; mi < 2; mi++) {
                    MMA16816(acc_o[mi][2*dn],     pf[mi][t], b0);
                    MMA16816(acc_o[mi][2*dn + 1], pf[mi][t], b1);
                }
            }
        }
        __syncthreads();
    }

    // ---- cross-pair reduction: ng=1 dumps O + lsum, ng=0 finalizes ----
    float* obuf = reinterpret_cast<float*>(sm + AKV0);          // 16KB (64x64)
    float* sbuf = reinterpret_cast<float*>(sm + AKV0 + 16384);  // 128 floats

#pragma unroll
    for (int mi = 0; mi < 2; mi++)
#pragma unroll
        for (int h = 0; h < 2; h++) {
            float v = lsum[mi][h];
            v += __shfl_xor_sync(0xffffffffu, v, 1);
            v += __shfl_xor_sync(0xffffffffu, v, 2);
            if ((lane & 3) == 0)
                sbuf[ng * 64 + m0w + mi * 16 + h * 8 + (lane >> 2)] = v;
        }

    if (ng == 1) {
#pragma unroll
        for (int mi = 0; mi < 2; mi++) {
            const int lr1 = m0w + mi * 16 + (lane >> 2);
            const int lr2 = lr1 + 8;
#pragma unroll
            for (int n = 0; n < 8; n++) {
                const int col = n * 8 + (lane & 3) * 2;
                float* d = acc_o[mi][n];
                float2 v1 = {d[0], d[1]}, v2 = {d[2], d[3]};
                *reinterpret_cast<float2*>(&obuf[lr1 * 64 + col]) = v1;
                *reinterpret_cast<float2*>(&obuf[lr2 * 64 + col]) = v2;
            }
        }
    }
    __syncthreads();

    if (ng == 0) {
#pragma unroll
        for (int mi = 0; mi < 2; mi++) {
            const int lr1 = m0w + mi * 16 + (lane >> 2);
            const int lr2 = lr1 + 8;
            const float i1 = 1.0f / (sbuf[lr1] + sbuf[64 + lr1]);
            const float i2 = 1.0f / (sbuf[lr2] + sbuf[64 + lr2]);
#pragma unroll
            for (int n = 0; n < 8; n++) {
                const int col = n * 8 + (lane & 3) * 2;
                float* d = acc_o[mi][n];
                float2 o1 = *reinterpret_cast<float2*>(&obuf[lr1 * 64 + col]);
                float2 o2 = *reinterpret_cast<float2*>(&obuf[lr2 * 64 + col]);
                size_t idx = (size_t)(q0 + lr1) * E + hoff + col;
                *reinterpret_cast<uint32_t*>(Cx + idx) =
                    pack_h2((d[0] + o1.x) * i1, (d[1] + o1.y) * i1);
                idx = (size_t)(q0 + lr2) * E + hoff + col;
                *reinterpret_cast<uint32_t*>(Cx + idx) =
                    pack_h2((d[2] + o2.x) * i2, (d[3] + o2.y) * i2);
            }
        }
    }
}

// ---------------- host side ----------------
extern "C" void kernel_launch(void* const* d_in, const int* in_sizes, int n_in,
                              void* d_out, int out_size)
{
    const float* values = (const float*)d_in[0];
    const float* keys   = (const float*)d_in[1];
    const float* query  = (const float*)d_in[2];
    const float* dist   = (const float*)d_in[3];
    const float* Wv     = (const float*)d_in[4];
    const float* Wk     = (const float*)d_in[5];
    const float* Wq     = (const float*)d_in[6];
    const float* Wo     = (const float*)d_in[7];
    const float* bo     = (const float*)d_in[8];
    float* out = (float*)d_out;

    __half *xq, *xk, *xv, *wq, *wk, *wv, *wo;
    __half *pq, *pk, *pv, *cx;
    __nv_bfloat16* biasbf;
    cudaGetSymbolAddress((void**)&xq, g_xq);
    cudaGetSymbolAddress((void**)&xk, g_xk);
    cudaGetSymbolAddress((void**)&xv, g_xv);
    cudaGetSymbolAddress((void**)&wq, g_wq);
    cudaGetSymbolAddress((void**)&wk, g_wk);
    cudaGetSymbolAddress((void**)&wv, g_wv);
    cudaGetSymbolAddress((void**)&wo, g_wo);
    cudaGetSymbolAddress((void**)&pq, g_pq);
    cudaGetSymbolAddress((void**)&pk, g_pk);
    cudaGetSymbolAddress((void**)&pv, g_pv);
    cudaGetSymbolAddress((void**)&cx, g_cx);
    cudaGetSymbolAddress((void**)&biasbf, g_biasbf);

    cudaFuncSetAttribute(gemm1_qkv, cudaFuncAttributeMaxDynamicSharedMemorySize, G1_SMEM);
    cudaFuncSetAttribute(gemm1_o,   cudaFuncAttributeMaxDynamicSharedMemorySize, G1_SMEM);
    cudaFuncSetAttribute(attn_tc,   cudaFuncAttributeMaxDynamicSharedMemorySize, ATTN_SMEM);

    // launches: 1 conv, 2 bias, 3 qkv, 4 attn, 5 o
    const int nConv = (3 * LE + 4 * EE) / 4 / 256;
    conv_all<<<nConv, 256>>>(query, keys, values, Wq, Wk, Wv, Wo,
                             xq, xk, xv, wq, wk, wv, wo);
    bias_prep<<<(L * L) / 4 / 256, 256>>>(dist, biasbf);

    dim3 gqkv(E / 128, L / 128, 3);   // 384 CTAs
    gemm1_qkv<<<gqkv, 256, G1_SMEM>>>(xq, wq, pq, xk, wk, pk, xv, wv, pv);

    attn_tc<<<dim3(L / 64, NH), 128, ATTN_SMEM>>>(pq, pk, pv, biasbf, cx);

    dim3 go(E / 128, L / 128);        // 128 CTAs
    gemm1_o<<<go, 256, G1_SMEM>>>(cx, wo, out, bo);
}

// round 15
// speedup vs baseline: 1.1310x; 1.0078x over previous
#include <cuda_runtime.h>
#include <cuda_fp16.h>
#include <cuda_bf16.h>
#include <cstdint>

// ---------------- problem constants ----------------
constexpr int L  = 2048;
constexpr int E  = 1024;
constexpr int NH = 16;
constexpr int HD = 64;
constexpr float KSCALE = 0.04508422002778011f;   // log2(e)/32

// ---------------- device scratch (all 1-term fp16) ----------------
__device__ __half g_xq[L * E], g_xk[L * E], g_xv[L * E];
__device__ __half g_wq[E * E], g_wk[E * E], g_wv[E * E], g_wo[E * E];
__device__ __half g_pq[L * E];                  // projected Q (scaled)
__device__ __half g_pk[L * E];                  // projected K
__device__ __half g_pv[L * E];                  // projected V
__device__ __half g_cx[L * E];                  // context
__device__ __nv_bfloat16 g_biasbf[(size_t)L * L];  // bias * log2e/32, bf16

// ---------------- helpers ----------------
__device__ __forceinline__ uint32_t s2u(const void* p) {
    uint32_t a;
    asm("{ .reg .u64 t; cvta.to.shared.u64 t, %1; cvt.u32.u64 %0, t; }"
        : "=r"(a) : "l"(p));
    return a;
}
__device__ __forceinline__ uint32_t sw128(uint32_t off) {
    return off ^ ((off >> 3) & 0x70);
}
__device__ __forceinline__ float ex2f(float x) {
    float r; asm("ex2.approx.f32 %0, %1;" : "=f"(r) : "f"(x)); return r;
}
__device__ __forceinline__ uint32_t pack_h2(float lo, float hi) {
    uint32_t r;
    asm("cvt.rn.f16x2.f32 %0, %1, %2;" : "=r"(r) : "f"(hi), "f"(lo));
    return r;
}
__device__ __forceinline__ uint32_t pack_bf2(float lo, float hi) {
    uint32_t r;
    asm("cvt.rn.bf16x2.f32 %0, %1, %2;" : "=r"(r) : "f"(hi), "f"(lo));
    return r;
}

#define CP_ASYNC16(dst, src) \
    asm volatile("cp.async.cg.shared.global [%0], [%1], 16;" :: "r"(dst), "l"(src))
#define CP_COMMIT() asm volatile("cp.async.commit_group;" ::: "memory")
#define CP_WAIT1()  asm volatile("cp.async.wait_group 1;" ::: "memory")
#define CP_WAIT0()  asm volatile("cp.async.wait_group 0;" ::: "memory")

#define LDSM4(r0, r1, r2, r3, a) \
    asm volatile("ldmatrix.sync.aligned.m8n8.x4.shared.b16 {%0,%1,%2,%3}, [%4];" \
        : "=r"(r0), "=r"(r1), "=r"(r2), "=r"(r3) : "r"(a))
#define LDSM4T(r0, r1, r2, r3, a) \
    asm volatile("ldmatrix.sync.aligned.m8n8.x4.trans.shared.b16 {%0,%1,%2,%3}, [%4];" \
        : "=r"(r0), "=r"(r1), "=r"(r2), "=r"(r3) : "r"(a))

#define MMA16816(d, a, b) \
    asm volatile("mma.sync.aligned.m16n8k16.row.col.f32.f16.f16.f32 " \
        "{%0,%1,%2,%3}, {%4,%5,%6,%7}, {%8,%9}, {%0,%1,%2,%3};" \
        : "+f"((d)[0]), "+f"((d)[1]), "+f"((d)[2]), "+f"((d)[3]) \
        : "r"((a)[0]), "r"((a)[1]), "r"((a)[2]), "r"((a)[3]), \
          "r"((b)[0]), "r"((b)[1]))

// cp.async one [128 x 64] f16 tile, 128 threads
__device__ __forceinline__ void cp_tile_h(uint32_t dst, const __half* src,
                                          int ld, int tid) {
#pragma unroll
    for (int i = 0; i < 8; i++) {
        int u   = i * 128 + tid;
        int row = u >> 3;
        int ch  = u & 7;
        uint32_t d = dst + sw128((uint32_t)(row * 128 + ch * 16));
        CP_ASYNC16(d, src + (size_t)row * ld + ch * 8);
    }
}

// cp.async one [64 x 64] f16 tile, 128 threads
__device__ __forceinline__ void cp_tile_q(uint32_t dst, const __half* src,
                                          int ld, int tid) {
#pragma unroll
    for (int i = 0; i < 4; i++) {
        int u   = i * 128 + tid;
        int row = u >> 3;
        int ch  = u & 7;
        uint32_t d = dst + sw128((uint32_t)(row * 128 + ch * 16));
        CP_ASYNC16(d, src + (size_t)row * ld + ch * 8);
    }
}

// ---------------- fused conversion ----------------
__device__ __forceinline__ void conv1_at(const float* s, __half* d, int i) {
    float4 v = *reinterpret_cast<const float4*>(s + i);
    uint2 o = { pack_h2(v.x, v.y), pack_h2(v.z, v.w) };
    *reinterpret_cast<uint2*>(d + i) = o;
}

constexpr int LE = L * E, EE = E * E;

__global__ void conv_all(const float* q, const float* k, const float* v,
                         const float* Wq, const float* Wk,
                         const float* Wv, const float* Wo,
                         __half* xq, __half* xk, __half* xv,
                         __half* wq, __half* wk, __half* wv, __half* wo)
{
    int i = (blockIdx.x * blockDim.x + threadIdx.x) * 4;
    if (i < LE) { conv1_at(q, xq, i); return; }
    i -= LE;
    if (i < LE) { conv1_at(k, xk, i); return; }
    i -= LE;
    if (i < LE) { conv1_at(v, xv, i); return; }
    i -= LE;
    if (i < EE) { conv1_at(Wq, wq, i); return; }
    i -= EE;
    if (i < EE) { conv1_at(Wk, wk, i); return; }
    i -= EE;
    if (i < EE) { conv1_at(Wv, wv, i); return; }
    i -= EE;
    conv1_at(Wo, wo, i);
}

// ---------------- bias table: bf16( log2e/32 * 1/(d+1) ) ----------------
__global__ void bias_prep(const float* __restrict__ d, __nv_bfloat16* __restrict__ b)
{
    int i = (blockIdx.x * blockDim.x + threadIdx.x) * 4;
    float4 v = *reinterpret_cast<const float4*>(d + i);
    float o0 = (v.x == 0.f) ? 0.f : KSCALE / (v.x + 1.f);
    float o1 = (v.y == 0.f) ? 0.f : KSCALE / (v.y + 1.f);
    float o2 = (v.z == 0.f) ? 0.f : KSCALE / (v.z + 1.f);
    float o3 = (v.w == 0.f) ? 0.f : KSCALE / (v.w + 1.f);
    uint2 o = { pack_bf2(o0, o1), pack_bf2(o2, o3) };
    *reinterpret_cast<uint2*>(b + i) = o;
}

// ---------------- 1-term GEMM core ----------------
// 128x128 CTA tile, 128 threads (2x2 warps of 64x64), 2 CTAs/SM.
// ratio-4 warp tile: per ks, 4 A-LDSM + 4 B-LDSM feed 32 MMAs.
constexpr int G1_SMEM = 65536;

template <typename EPI>
__device__ __forceinline__ void gemm1_body(const __half* A, const __half* B,
                                           int m0, int n0, EPI epi)
{
    extern __shared__ char sm[];
    const uint32_t sb = s2u(sm);
    const int tid  = threadIdx.x;
    const int wid  = tid >> 5;
    const int lane = tid & 31;
    const int m0w  = (wid >> 1) * 64;
    const int n0w  = (wid & 1) * 64;
    const int sub = lane >> 3, lr = lane & 7;
    const int K = E;

    float acc[4][8][4];
#pragma unroll
    for (int i = 0; i < 4; i++)
#pragma unroll
        for (int j = 0; j < 8; j++)
#pragma unroll
            for (int k = 0; k < 4; k++) acc[i][j][k] = 0.f;

    const int NC = K / 64;
    cp_tile_h(sb,         A + (size_t)m0 * K, K, tid);
    cp_tile_h(sb + 16384, B + (size_t)n0 * K, K, tid);
    CP_COMMIT();

    for (int kc = 0; kc < NC; kc++) {
        if (kc + 1 < NC) {
            uint32_t base = sb + ((kc + 1) & 1) * 32768;
            const int k0 = (kc + 1) * 64;
            cp_tile_h(base,         A + (size_t)m0 * K + k0, K, tid);
            cp_tile_h(base + 16384, B + (size_t)n0 * K + k0, K, tid);
            CP_COMMIT();
            CP_WAIT1();
        } else {
            CP_WAIT0();
        }
        __syncthreads();

        const uint32_t base = sb + (kc & 1) * 32768;
#pragma unroll
        for (int ks = 0; ks < 4; ks++) {
            const int ch = ks * 2 + (sub >> 1);
            uint32_t ah[4][4], bh[8][2];
#pragma unroll
            for (int mi = 0; mi < 4; mi++) {
                int r = m0w + mi * 16 + (sub & 1) * 8 + lr;
                uint32_t off = sw128((uint32_t)(r * 128 + ch * 16));
                LDSM4(ah[mi][0], ah[mi][1], ah[mi][2], ah[mi][3], base + off);
            }
#pragma unroll
            for (int ng = 0; ng < 4; ng++) {
                int r = n0w + ng * 16 + (sub & 1) * 8 + lr;
                uint32_t off = sw128((uint32_t)(r * 128 + ch * 16));
                uint32_t t0, t1, t2, t3;
                LDSM4(t0, t1, t2, t3, base + 16384 + off);
                bh[2*ng][0] = t0; bh[2*ng][1] = t2;
                bh[2*ng+1][0] = t1; bh[2*ng+1][1] = t3;
            }
#pragma unroll
            for (int mi = 0; mi < 4; mi++)
#pragma unroll
                for (int ni = 0; ni < 8; ni++)
                    MMA16816(acc[mi][ni], ah[mi], bh[ni]);
        }
        __syncthreads();
    }

#pragma unroll
    for (int mi = 0; mi < 4; mi++) {
        int r1 = m0 + m0w + mi * 16 + (lane >> 2);
#pragma unroll
        for (int ni = 0; ni < 8; ni++) {
            int col = n0 + n0w + ni * 8 + (lane & 3) * 2;
            epi(acc[mi][ni], r1, col);
        }
    }
}

__global__ void __launch_bounds__(128, 2)
gemm1_qkv(const __half* __restrict__ xq, const __half* __restrict__ wq,
          __half* __restrict__ pq,
          const __half* __restrict__ xk, const __half* __restrict__ wk,
          __half* __restrict__ pk,
          const __half* __restrict__ xv, const __half* __restrict__ wv,
          __half* __restrict__ pv)
{
    const __half* A = (blockIdx.z == 0) ? xq : (blockIdx.z == 1) ? xk : xv;
    const __half* B = (blockIdx.z == 0) ? wq : (blockIdx.z == 1) ? wk : wv;
    __half* C       = (blockIdx.z == 0) ? pq : (blockIdx.z == 1) ? pk : pv;
    const float oscale = (blockIdx.z == 0) ? KSCALE : 1.0f;
    const int m0 = blockIdx.y * 128, n0 = blockIdx.x * 128;

    gemm1_body(A, B, m0, n0,
        [&](float* d, int r1, int col) {
            *reinterpret_cast<uint32_t*>(C + (size_t)r1 * E + col) =
                pack_h2(d[0] * oscale, d[1] * oscale);
            *reinterpret_cast<uint32_t*>(C + (size_t)(r1 + 8) * E + col) =
                pack_h2(d[2] * oscale, d[3] * oscale);
        });
}

__global__ void __launch_bounds__(128, 2)
gemm1_o(const __half* __restrict__ cx, const __half* __restrict__ wo,
        float* __restrict__ out, const float* __restrict__ bvec)
{
    const int m0 = blockIdx.y * 128, n0 = blockIdx.x * 128;
    gemm1_body(cx, wo, m0, n0,
        [&](float* d, int r1, int col) {
            float2 bv = *reinterpret_cast<const float2*>(bvec + col);
            float2 o1 = {d[0] + bv.x, d[1] + bv.y};
            float2 o2 = {d[2] + bv.x, d[3] + bv.y};
            *reinterpret_cast<float2*>(out + (size_t)r1 * E + col) = o1;
            *reinterpret_cast<float2*>(out + (size_t)(r1 + 8) * E + col) = o2;
        });
}

// ---------------- attention (R14: register P, 64q CTA, 128 thr, 2 CTA/SM) ----
constexpr uint32_t AQ   = 0;
constexpr uint32_t AKV0 = 8192;
constexpr uint32_t AKV1 = 40960;
constexpr int ATTN_SMEM = 73728;

__global__ void __launch_bounds__(128, 2)
attn_tc(const __half* __restrict__ Q,
        const __half* __restrict__ Kp,
        const __half* __restrict__ Vp,
        const __nv_bfloat16* __restrict__ biasbf,
        __half* __restrict__ Cx)
{
    extern __shared__ char sm[];
    const uint32_t sb = s2u(sm);
    const int tid  = threadIdx.x;
    const int wid  = tid >> 5;
    const int lane = tid & 31;
    const int mg   = wid >> 1;          // 0..1, rows mg*32
    const int ng   = wid & 1;           // 0..1, keys ng*64
    const int m0w  = mg * 32;
    const int kbase = ng * 64;
    const int q0   = blockIdx.x * 64;
    const int hoff = blockIdx.y * HD;
    const int sub = lane >> 3, lr = lane & 7;

    // prologue: Q group, then KV0 group
    cp_tile_q(sb + AQ, Q + (size_t)q0 * E + hoff, E, tid);
    CP_COMMIT();
    cp_tile_h(sb + AKV0,         Kp + hoff, E, tid);
    cp_tile_h(sb + AKV0 + 16384, Vp + hoff, E, tid);
    CP_COMMIT();
    CP_WAIT1();            // Q group done
    __syncthreads();

    // Q fragments in registers: [ks][mi][4], rows m0w + mi*16
    uint32_t qf[4][2][4];
#pragma unroll
    for (int ks = 0; ks < 4; ks++) {
        const int ch = ks * 2 + (sub >> 1);
#pragma unroll
        for (int mi = 0; mi < 2; mi++) {
            int r = m0w + mi * 16 + (sub & 1) * 8 + lr;
            uint32_t off = sw128((uint32_t)(r * 128 + ch * 16));
            LDSM4(qf[ks][mi][0], qf[ks][mi][1], qf[ks][mi][2], qf[ks][mi][3],
                  sb + AQ + off);
        }
    }

    float acc_o[2][8][4];          // 32 rows x 64 d-cols (partial over keys)
#pragma unroll
    for (int i = 0; i < 2; i++)
#pragma unroll
        for (int j = 0; j < 8; j++)
#pragma unroll
            for (int k = 0; k < 4; k++) acc_o[i][j][k] = 0.f;
    float lsum[2][2];
    lsum[0][0] = lsum[0][1] = lsum[1][0] = lsum[1][1] = 0.f;

    for (int kt = 0; kt < L / 128; kt++) {
        const int kb = kt * 128;
        if (kt + 1 < L / 128) {
            uint32_t base = sb + (((kt + 1) & 1) ? AKV1 : AKV0);
            const size_t ro = (size_t)(kb + 128) * E + hoff;
            cp_tile_h(base,         Kp + ro, E, tid);
            cp_tile_h(base + 16384, Vp + ro, E, tid);
            CP_COMMIT();
            CP_WAIT1();
        } else {
            CP_WAIT0();
        }
        __syncthreads();

        const uint32_t bkv = sb + ((kt & 1) ? AKV1 : AKV0);

        // ---- S = Q @ K^T over this warp's 64 keys ----
        float acc_s[2][8][4];
#pragma unroll
        for (int i = 0; i < 2; i++)
#pragma unroll
            for (int j = 0; j < 8; j++)
#pragma unroll
                for (int k = 0; k < 4; k++) acc_s[i][j][k] = 0.f;

#pragma unroll
        for (int ks = 0; ks < 4; ks++) {
            const int ch = ks * 2 + (sub >> 1);
            uint32_t bh[8][2];
#pragma unroll
            for (int kg = 0; kg < 4; kg++) {
                int r = kbase + kg * 16 + (sub & 1) * 8 + lr;
                uint32_t off = sw128((uint32_t)(r * 128 + ch * 16));
                uint32_t t0, t1, t2, t3;
                LDSM4(t0, t1, t2, t3, bkv + off);
                bh[2*kg][0] = t0; bh[2*kg][1] = t2;
                bh[2*kg+1][0] = t1; bh[2*kg+1][1] = t3;
            }
#pragma unroll
            for (int mi = 0; mi < 2; mi++)
#pragma unroll
                for (int n = 0; n < 8; n++)
                    MMA16816(acc_s[mi][n], qf[ks][mi], bh[n]);
        }

        // ---- p = ex2(S + bias) in registers; pack to PV A-fragments ----
        uint32_t pf[2][4][4];
#pragma unroll
        for (int mi = 0; mi < 2; mi++) {
            const int lr1 = m0w + mi * 16 + (lane >> 2);
            const int lr2 = lr1 + 8;
            const uint32_t* bp1 = reinterpret_cast<const uint32_t*>(
                biasbf + (size_t)(q0 + lr1) * L + kb + kbase);
            const uint32_t* bp2 = reinterpret_cast<const uint32_t*>(
                biasbf + (size_t)(q0 + lr2) * L + kb + kbase);
#pragma unroll
            for (int n = 0; n < 8; n++) {
                const int lc = n * 8 + (lane & 3) * 2;
                uint32_t pk1 = bp1[lc >> 1];
                uint32_t pk2 = bp2[lc >> 1];
                float* d = acc_s[mi][n];
                float p0 = ex2f(d[0] + __uint_as_float(pk1 << 16));
                float p1 = ex2f(d[1] + __uint_as_float(pk1 & 0xffff0000u));
                float p2 = ex2f(d[2] + __uint_as_float(pk2 << 16));
                float p3 = ex2f(d[3] + __uint_as_float(pk2 & 0xffff0000u));
                lsum[mi][0] += p0 + p1;
                lsum[mi][1] += p2 + p3;
                const int t = n >> 1, j = n & 1;
                pf[mi][t][2*j]     = pack_h2(p0, p1);   // rows r   (a0/a2)
                pf[mi][t][2*j + 1] = pack_h2(p2, p3);   // rows r+8 (a1/a3)
            }
        }

        // ---- O += P @ V (registers -> MMA, V via LDSM4T) ----
#pragma unroll
        for (int t = 0; t < 4; t++) {
            int rv = kbase + t * 16 + (sub >> 1) * 8 + lr;
#pragma unroll
            for (int dn = 0; dn < 4; dn++) {
                int cv = dn * 2 + (sub & 1);
                uint32_t off = sw128((uint32_t)(rv * 128 + cv * 16));
                uint32_t t0, t1, t2, t3;
                LDSM4T(t0, t1, t2, t3, bkv + 16384 + off);
                uint32_t b0[2] = {t0, t2}, b1[2] = {t1, t3};
#pragma unroll
                for (int mi = 0; mi < 2; mi++) {
                    MMA16816(acc_o[mi][2*dn],     pf[mi][t], b0);
                    MMA16816(acc_o[mi][2*dn + 1], pf[mi][t], b1);
                }
            }
        }
        __syncthreads();
    }

    // ---- cross-pair reduction: ng=1 dumps O + lsum, ng=0 finalizes ----
    float* obuf = reinterpret_cast<float*>(sm + AKV0);          // 16KB (64x64)
    float* sbuf = reinterpret_cast<float*>(sm + AKV0 + 16384);  // 128 floats

#pragma unroll
    for (int mi = 0; mi < 2; mi++)
#pragma unroll
        for (int h = 0; h < 2; h++) {
            float v = lsum[mi][h];
            v += __shfl_xor_sync(0xffffffffu, v, 1);
            v += __shfl_xor_sync(0xffffffffu, v, 2);
            if ((lane & 3) == 0)
                sbuf[ng * 64 + m0w + mi * 16 + h * 8 + (lane >> 2)] = v;
        }

    if (ng == 1) {
#pragma unroll
        for (int mi = 0; mi < 2; mi++) {
            const int lr1 = m0w + mi * 16 + (lane >> 2);
            const int lr2 = lr1 + 8;
#pragma unroll
            for (int n = 0; n < 8; n++) {
                const int col = n * 8 + (lane & 3) * 2;
                float* d = acc_o[mi][n];
                float2 v1 = {d[0], d[1]}, v2 = {d[2], d[3]};
                *reinterpret_cast<float2*>(&obuf[lr1 * 64 + col]) = v1;
                *reinterpret_cast<float2*>(&obuf[lr2 * 64 + col]) = v2;
            }
        }
    }
    __syncthreads();

    if (ng == 0) {
#pragma unroll
        for (int mi = 0; mi < 2; mi++) {
            const int lr1 = m0w + mi * 16 + (lane >> 2);
            const int lr2 = lr1 + 8;
            const float i1 = 1.0f / (sbuf[lr1] + sbuf[64 + lr1]);
            const float i2 = 1.0f / (sbuf[lr2] + sbuf[64 + lr2]);
#pragma unroll
            for (int n = 0; n < 8; n++) {
                const int col = n * 8 + (lane & 3) * 2;
                float* d = acc_o[mi][n];
                float2 o1 = *reinterpret_cast<float2*>(&obuf[lr1 * 64 + col]);
                float2 o2 = *reinterpret_cast<float2*>(&obuf[lr2 * 64 + col]);
                size_t idx = (size_t)(q0 + lr1) * E + hoff + col;
                *reinterpret_cast<uint32_t*>(Cx + idx) =
                    pack_h2((d[0] + o1.x) * i1, (d[1] + o1.y) * i1);
                idx = (size_t)(q0 + lr2) * E + hoff + col;
                *reinterpret_cast<uint32_t*>(Cx + idx) =
                    pack_h2((d[2] + o2.x) * i2, (d[3] + o2.y) * i2);
            }
        }
    }
}

// ---------------- host side ----------------
extern "C" void kernel_launch(void* const* d_in, const int* in_sizes, int n_in,
                              void* d_out, int out_size)
{
    const float* values = (const float*)d_in[0];
    const float* keys   = (const float*)d_in[1];
    const float* query  = (const float*)d_in[2];
    const float* dist   = (const float*)d_in[3];
    const float* Wv     = (const float*)d_in[4];
    const float* Wk     = (const float*)d_in[5];
    const float* Wq     = (const float*)d_in[6];
    const float* Wo     = (const float*)d_in[7];
    const float* bo     = (const float*)d_in[8];
    float* out = (float*)d_out;

    __half *xq, *xk, *xv, *wq, *wk, *wv, *wo;
    __half *pq, *pk, *pv, *cx;
    __nv_bfloat16* biasbf;
    cudaGetSymbolAddress((void**)&xq, g_xq);
    cudaGetSymbolAddress((void**)&xk, g_xk);
    cudaGetSymbolAddress((void**)&xv, g_xv);
    cudaGetSymbolAddress((void**)&wq, g_wq);
    cudaGetSymbolAddress((void**)&wk, g_wk);
    cudaGetSymbolAddress((void**)&wv, g_wv);
    cudaGetSymbolAddress((void**)&wo, g_wo);
    cudaGetSymbolAddress((void**)&pq, g_pq);
    cudaGetSymbolAddress((void**)&pk, g_pk);
    cudaGetSymbolAddress((void**)&pv, g_pv);
    cudaGetSymbolAddress((void**)&cx, g_cx);
    cudaGetSymbolAddress((void**)&biasbf, g_biasbf);

    cudaFuncSetAttribute(gemm1_qkv, cudaFuncAttributeMaxDynamicSharedMemorySize, G1_SMEM);
    cudaFuncSetAttribute(gemm1_o,   cudaFuncAttributeMaxDynamicSharedMemorySize, G1_SMEM);
    cudaFuncSetAttribute(attn_tc,   cudaFuncAttributeMaxDynamicSharedMemorySize, ATTN_SMEM);

    // launches: 1 conv, 2 bias, 3 qkv, 4 attn, 5 o
    const int nConv = (3 * LE + 4 * EE) / 4 / 256;
    conv_all<<<nConv, 256>>>(query, keys, values, Wq, Wk, Wv, Wo,
                             xq, xk, xv, wq, wk, wv, wo);
    bias_prep<<<(L * L) / 4 / 256, 256>>>(dist, biasbf);

    dim3 gqkv(E / 128, L / 128, 3);   // 384 CTAs
    gemm1_qkv<<<gqkv, 128, G1_SMEM>>>(xq, wq, pq, xk, wk, pk, xv, wv, pv);

    attn_tc<<<dim3(L / 64, NH), 128, ATTN_SMEM>>>(pq, pk, pv, biasbf, cx);

    dim3 go(E / 128, L / 128);        // 128 CTAs
    gemm1_o<<<go, 128, G1_SMEM>>>(cx, wo, out, bo);
}

// round 16
// speedup vs baseline: 1.2228x; 1.0812x over previous
#include <cuda_runtime.h>
#include <cuda_fp16.h>
#include <cuda_bf16.h>
#include <cstdint>

// ---------------- problem constants ----------------
constexpr int L  = 2048;
constexpr int E  = 1024;
constexpr int NH = 16;
constexpr int HD = 64;
constexpr float KSCALE = 0.04508422002778011f;   // log2(e)/32

// ---------------- device scratch (all 1-term fp16) ----------------
__device__ __half g_xq[L * E], g_xk[L * E], g_xv[L * E];
__device__ __half g_wq[E * E], g_wk[E * E], g_wv[E * E], g_wo[E * E];
__device__ __half g_pq[L * E];                  // projected Q (scaled)
__device__ __half g_pk[L * E];                  // projected K
__device__ __half g_pv[L * E];                  // projected V
__device__ __half g_cx[L * E];                  // context
__device__ __nv_bfloat16 g_biasbf[(size_t)L * L];  // bias * log2e/32, bf16

// ---------------- helpers ----------------
__device__ __forceinline__ uint32_t s2u(const void* p) {
    uint32_t a;
    asm("{ .reg .u64 t; cvta.to.shared.u64 t, %1; cvt.u32.u64 %0, t; }"
        : "=r"(a) : "l"(p));
    return a;
}
__device__ __forceinline__ uint32_t sw128(uint32_t off) {
    return off ^ ((off >> 3) & 0x70);
}
__device__ __forceinline__ float ex2f(float x) {
    float r; asm("ex2.approx.f32 %0, %1;" : "=f"(r) : "f"(x)); return r;
}
__device__ __forceinline__ uint32_t pack_h2(float lo, float hi) {
    uint32_t r;
    asm("cvt.rn.f16x2.f32 %0, %1, %2;" : "=r"(r) : "f"(hi), "f"(lo));
    return r;
}
__device__ __forceinline__ uint32_t pack_bf2(float lo, float hi) {
    uint32_t r;
    asm("cvt.rn.bf16x2.f32 %0, %1, %2;" : "=r"(r) : "f"(hi), "f"(lo));
    return r;
}

#define CP_ASYNC16(dst, src) \
    asm volatile("cp.async.cg.shared.global [%0], [%1], 16;" :: "r"(dst), "l"(src))
#define CP_COMMIT() asm volatile("cp.async.commit_group;" ::: "memory")
#define CP_WAIT1()  asm volatile("cp.async.wait_group 1;" ::: "memory")
#define CP_WAIT0()  asm volatile("cp.async.wait_group 0;" ::: "memory")

#define LDSM4(r0, r1, r2, r3, a) \
    asm volatile("ldmatrix.sync.aligned.m8n8.x4.shared.b16 {%0,%1,%2,%3}, [%4];" \
        : "=r"(r0), "=r"(r1), "=r"(r2), "=r"(r3) : "r"(a))
#define LDSM4T(r0, r1, r2, r3, a) \
    asm volatile("ldmatrix.sync.aligned.m8n8.x4.trans.shared.b16 {%0,%1,%2,%3}, [%4];" \
        : "=r"(r0), "=r"(r1), "=r"(r2), "=r"(r3) : "r"(a))

#define MMA16816(d, a, b) \
    asm volatile("mma.sync.aligned.m16n8k16.row.col.f32.f16.f16.f32 " \
        "{%0,%1,%2,%3}, {%4,%5,%6,%7}, {%8,%9}, {%0,%1,%2,%3};" \
        : "+f"((d)[0]), "+f"((d)[1]), "+f"((d)[2]), "+f"((d)[3]) \
        : "r"((a)[0]), "r"((a)[1]), "r"((a)[2]), "r"((a)[3]), \
          "r"((b)[0]), "r"((b)[1]))

// cp.async one [128 x 64] f16 tile, 128 threads
__device__ __forceinline__ void cp_tile_h(uint32_t dst, const __half* src,
                                          int ld, int tid) {
#pragma unroll
    for (int i = 0; i < 8; i++) {
        int u   = i * 128 + tid;
        int row = u >> 3;
        int ch  = u & 7;
        uint32_t d = dst + sw128((uint32_t)(row * 128 + ch * 16));
        CP_ASYNC16(d, src + (size_t)row * ld + ch * 8);
    }
}

// cp.async one [64 x 64] f16 tile, 128 threads
__device__ __forceinline__ void cp_tile_q(uint32_t dst, const __half* src,
                                          int ld, int tid) {
#pragma unroll
    for (int i = 0; i < 4; i++) {
        int u   = i * 128 + tid;
        int row = u >> 3;
        int ch  = u & 7;
        uint32_t d = dst + sw128((uint32_t)(row * 128 + ch * 16));
        CP_ASYNC16(d, src + (size_t)row * ld + ch * 8);
    }
}

// cp.async bias slice [64 rows x 128 keys] bf16, row stride 272B (pad), 128 thr
constexpr uint32_t BSTRIDE = 272;
__device__ __forceinline__ void cp_bias(uint32_t dst,
                                        const __nv_bfloat16* src,   // row 0, key 0
                                        int tid) {
#pragma unroll
    for (int i = 0; i < 8; i++) {
        int u   = i * 128 + tid;
        int row = u >> 4;          // 0..63
        int ch  = u & 15;          // 16B chunk within 256B row
        uint32_t d = dst + row * BSTRIDE + ch * 16;
        CP_ASYNC16(d, src + (size_t)row * L + ch * 8);
    }
}

// ---------------- fused conversion + bias prep (single launch) ----------------
__device__ __forceinline__ void conv1_at(const float* s, __half* d, int i) {
    float4 v = *reinterpret_cast<const float4*>(s + i);
    uint2 o = { pack_h2(v.x, v.y), pack_h2(v.z, v.w) };
    *reinterpret_cast<uint2*>(d + i) = o;
}

constexpr int LE = L * E, EE = E * E;

__global__ void conv_all(const float* q, const float* k, const float* v,
                         const float* Wq, const float* Wk,
                         const float* Wv, const float* Wo,
                         const float* dist,
                         __half* xq, __half* xk, __half* xv,
                         __half* wq, __half* wk, __half* wv, __half* wo,
                         __nv_bfloat16* biasbf)
{
    int i = (blockIdx.x * blockDim.x + threadIdx.x) * 4;
    if (i < LE) { conv1_at(q, xq, i); return; }
    i -= LE;
    if (i < LE) { conv1_at(k, xk, i); return; }
    i -= LE;
    if (i < LE) { conv1_at(v, xv, i); return; }
    i -= LE;
    if (i < EE) { conv1_at(Wq, wq, i); return; }
    i -= EE;
    if (i < EE) { conv1_at(Wk, wk, i); return; }
    i -= EE;
    if (i < EE) { conv1_at(Wv, wv, i); return; }
    i -= EE;
    if (i < EE) { conv1_at(Wo, wo, i); return; }
    i -= EE;
    // bias table: bf16( log2e/32 * 1/(d+1) )
    float4 v4 = *reinterpret_cast<const float4*>(dist + i);
    float o0 = (v4.x == 0.f) ? 0.f : KSCALE / (v4.x + 1.f);
    float o1 = (v4.y == 0.f) ? 0.f : KSCALE / (v4.y + 1.f);
    float o2 = (v4.z == 0.f) ? 0.f : KSCALE / (v4.z + 1.f);
    float o3 = (v4.w == 0.f) ? 0.f : KSCALE / (v4.w + 1.f);
    uint2 o = { pack_bf2(o0, o1), pack_bf2(o2, o3) };
    *reinterpret_cast<uint2*>(biasbf + i) = o;
}

// ---------------- 1-term GEMM core ----------------
// 128x128 CTA tile, 128 threads (2x2 warps of 64x64), 2 CTAs/SM.
constexpr int G1_SMEM = 65536;

template <typename EPI>
__device__ __forceinline__ void gemm1_body(const __half* A, const __half* B,
                                           int m0, int n0, EPI epi)
{
    extern __shared__ char sm[];
    const uint32_t sb = s2u(sm);
    const int tid  = threadIdx.x;
    const int wid  = tid >> 5;
    const int lane = tid & 31;
    const int m0w  = (wid >> 1) * 64;
    const int n0w  = (wid & 1) * 64;
    const int sub = lane >> 3, lr = lane & 7;
    const int K = E;

    float acc[4][8][4];
#pragma unroll
    for (int i = 0; i < 4; i++)
#pragma unroll
        for (int j = 0; j < 8; j++)
#pragma unroll
            for (int k = 0; k < 4; k++) acc[i][j][k] = 0.f;

    const int NC = K / 64;
    cp_tile_h(sb,         A + (size_t)m0 * K, K, tid);
    cp_tile_h(sb + 16384, B + (size_t)n0 * K, K, tid);
    CP_COMMIT();

    for (int kc = 0; kc < NC; kc++) {
        if (kc + 1 < NC) {
            uint32_t base = sb + ((kc + 1) & 1) * 32768;
            const int k0 = (kc + 1) * 64;
            cp_tile_h(base,         A + (size_t)m0 * K + k0, K, tid);
            cp_tile_h(base + 16384, B + (size_t)n0 * K + k0, K, tid);
            CP_COMMIT();
            CP_WAIT1();
        } else {
            CP_WAIT0();
        }
        __syncthreads();

        const uint32_t base = sb + (kc & 1) * 32768;
#pragma unroll
        for (int ks = 0; ks < 4; ks++) {
            const int ch = ks * 2 + (sub >> 1);
            uint32_t ah[4][4], bh[8][2];
#pragma unroll
            for (int mi = 0; mi < 4; mi++) {
                int r = m0w + mi * 16 + (sub & 1) * 8 + lr;
                uint32_t off = sw128((uint32_t)(r * 128 + ch * 16));
                LDSM4(ah[mi][0], ah[mi][1], ah[mi][2], ah[mi][3], base + off);
            }
#pragma unroll
            for (int ng = 0; ng < 4; ng++) {
                int r = n0w + ng * 16 + (sub & 1) * 8 + lr;
                uint32_t off = sw128((uint32_t)(r * 128 + ch * 16));
                uint32_t t0, t1, t2, t3;
                LDSM4(t0, t1, t2, t3, base + 16384 + off);
                bh[2*ng][0] = t0; bh[2*ng][1] = t2;
                bh[2*ng+1][0] = t1; bh[2*ng+1][1] = t3;
            }
#pragma unroll
            for (int mi = 0; mi < 4; mi++)
#pragma unroll
                for (int ni = 0; ni < 8; ni++)
                    MMA16816(acc[mi][ni], ah[mi], bh[ni]);
        }
        __syncthreads();
    }

#pragma unroll
    for (int mi = 0; mi < 4; mi++) {
        int r1 = m0 + m0w + mi * 16 + (lane >> 2);
#pragma unroll
        for (int ni = 0; ni < 8; ni++) {
            int col = n0 + n0w + ni * 8 + (lane & 3) * 2;
            epi(acc[mi][ni], r1, col);
        }
    }
}

__global__ void __launch_bounds__(128, 2)
gemm1_qkv(const __half* __restrict__ xq, const __half* __restrict__ wq,
          __half* __restrict__ pq,
          const __half* __restrict__ xk, const __half* __restrict__ wk,
          __half* __restrict__ pk,
          const __half* __restrict__ xv, const __half* __restrict__ wv,
          __half* __restrict__ pv)
{
    const __half* A = (blockIdx.z == 0) ? xq : (blockIdx.z == 1) ? xk : xv;
    const __half* B = (blockIdx.z == 0) ? wq : (blockIdx.z == 1) ? wk : wv;
    __half* C       = (blockIdx.z == 0) ? pq : (blockIdx.z == 1) ? pk : pv;
    const float oscale = (blockIdx.z == 0) ? KSCALE : 1.0f;
    const int m0 = blockIdx.y * 128, n0 = blockIdx.x * 128;

    gemm1_body(A, B, m0, n0,
        [&](float* d, int r1, int col) {
            *reinterpret_cast<uint32_t*>(C + (size_t)r1 * E + col) =
                pack_h2(d[0] * oscale, d[1] * oscale);
            *reinterpret_cast<uint32_t*>(C + (size_t)(r1 + 8) * E + col) =
                pack_h2(d[2] * oscale, d[3] * oscale);
        });
}

__global__ void __launch_bounds__(128, 2)
gemm1_o(const __half* __restrict__ cx, const __half* __restrict__ wo,
        float* __restrict__ out, const float* __restrict__ bvec)
{
    const int m0 = blockIdx.y * 128, n0 = blockIdx.x * 128;
    gemm1_body(cx, wo, m0, n0,
        [&](float* d, int r1, int col) {
            float2 bv = *reinterpret_cast<const float2*>(bvec + col);
            float2 o1 = {d[0] + bv.x, d[1] + bv.y};
            float2 o2 = {d[2] + bv.x, d[3] + bv.y};
            *reinterpret_cast<float2*>(out + (size_t)r1 * E + col) = o1;
            *reinterpret_cast<float2*>(out + (size_t)(r1 + 8) * E + col) = o2;
        });
}

// ---------------- attention ----------------
// R14 structure (register P, 64q CTA, 128 thr, 2 CTA/SM) + bias in the
// cp.async pipeline: each stage carries K(16K) | V(16K) | bias(17K, 272B rows).
// smem: Q(8K) | stage0(49K) | stage1(49K) = 106KB -> 212KB for 2 CTAs.
constexpr uint32_t AQ    = 0;
constexpr uint32_t ASTG0 = 8192;
constexpr uint32_t STG_SZ = 16384 + 16384 + 64 * BSTRIDE;   // 50176
constexpr uint32_t ASTG1 = ASTG0 + STG_SZ;                  // 58368
constexpr uint32_t OFF_V = 16384;
constexpr uint32_t OFF_B = 32768;
constexpr int ATTN_SMEM = (int)(ASTG1 + STG_SZ);            // 108544

__global__ void __launch_bounds__(128, 2)
attn_tc(const __half* __restrict__ Q,
        const __half* __restrict__ Kp,
        const __half* __restrict__ Vp,
        const __nv_bfloat16* __restrict__ biasbf,
        __half* __restrict__ Cx)
{
    extern __shared__ char sm[];
    const uint32_t sb = s2u(sm);
    const int tid  = threadIdx.x;
    const int wid  = tid >> 5;
    const int lane = tid & 31;
    const int mg   = wid >> 1;          // 0..1, rows mg*32
    const int ng   = wid & 1;           // 0..1, keys ng*64
    const int m0w  = mg * 32;
    const int kbase = ng * 64;
    const int q0   = blockIdx.x * 64;
    const int hoff = blockIdx.y * HD;
    const int sub = lane >> 3, lr = lane & 7;
    const __nv_bfloat16* brow0 = biasbf + (size_t)q0 * L;   // CTA's bias rows

    // prologue: Q group, then stage0 group (K,V,bias for tile 0)
    cp_tile_q(sb + AQ, Q + (size_t)q0 * E + hoff, E, tid);
    CP_COMMIT();
    cp_tile_h(sb + ASTG0,         Kp + hoff, E, tid);
    cp_tile_h(sb + ASTG0 + OFF_V, Vp + hoff, E, tid);
    cp_bias  (sb + ASTG0 + OFF_B, brow0, tid);
    CP_COMMIT();
    CP_WAIT1();            // Q group done
    __syncthreads();

    // Q fragments in registers: [ks][mi][4], rows m0w + mi*16
    uint32_t qf[4][2][4];
#pragma unroll
    for (int ks = 0; ks < 4; ks++) {
        const int ch = ks * 2 + (sub >> 1);
#pragma unroll
        for (int mi = 0; mi < 2; mi++) {
            int r = m0w + mi * 16 + (sub & 1) * 8 + lr;
            uint32_t off = sw128((uint32_t)(r * 128 + ch * 16));
            LDSM4(qf[ks][mi][0], qf[ks][mi][1], qf[ks][mi][2], qf[ks][mi][3],
                  sb + AQ + off);
        }
    }

    float acc_o[2][8][4];
#pragma unroll
    for (int i = 0; i < 2; i++)
#pragma unroll
        for (int j = 0; j < 8; j++)
#pragma unroll
            for (int k = 0; k < 4; k++) acc_o[i][j][k] = 0.f;
    float lsum[2][2];
    lsum[0][0] = lsum[0][1] = lsum[1][0] = lsum[1][1] = 0.f;

    for (int kt = 0; kt < L / 128; kt++) {
        const int kb = kt * 128;
        if (kt + 1 < L / 128) {
            uint32_t base = sb + (((kt + 1) & 1) ? ASTG1 : ASTG0);
            const size_t ro = (size_t)(kb + 128) * E + hoff;
            cp_tile_h(base,         Kp + ro, E, tid);
            cp_tile_h(base + OFF_V, Vp + ro, E, tid);
            cp_bias  (base + OFF_B, brow0 + kb + 128, tid);
            CP_COMMIT();
            CP_WAIT1();
        } else {
            CP_WAIT0();
        }
        __syncthreads();

        const uint32_t bkv = sb + ((kt & 1) ? ASTG1 : ASTG0);

        // ---- S = Q @ K^T over this warp's 64 keys ----
        float acc_s[2][8][4];
#pragma unroll
        for (int i = 0; i < 2; i++)
#pragma unroll
            for (int j = 0; j < 8; j++)
#pragma unroll
                for (int k = 0; k < 4; k++) acc_s[i][j][k] = 0.f;

#pragma unroll
        for (int ks = 0; ks < 4; ks++) {
            const int ch = ks * 2 + (sub >> 1);
            uint32_t bh[8][2];
#pragma unroll
            for (int kg = 0; kg < 4; kg++) {
                int r = kbase + kg * 16 + (sub & 1) * 8 + lr;
                uint32_t off = sw128((uint32_t)(r * 128 + ch * 16));
                uint32_t t0, t1, t2, t3;
                LDSM4(t0, t1, t2, t3, bkv + off);
                bh[2*kg][0] = t0; bh[2*kg][1] = t2;
                bh[2*kg+1][0] = t1; bh[2*kg+1][1] = t3;
            }
#pragma unroll
            for (int mi = 0; mi < 2; mi++)
#pragma unroll
                for (int n = 0; n < 8; n++)
                    MMA16816(acc_s[mi][n], qf[ks][mi], bh[n]);
        }

        // ---- p = ex2(S + bias[smem]) in registers; pack to PV A-frags ----
        uint32_t pf[2][4][4];
#pragma unroll
        for (int mi = 0; mi < 2; mi++) {
            const int lr1 = m0w + mi * 16 + (lane >> 2);   // local row 0..63
            const int lr2 = lr1 + 8;
            const uint32_t b1 = bkv + OFF_B + (uint32_t)lr1 * BSTRIDE + kbase * 2;
            const uint32_t b2 = bkv + OFF_B + (uint32_t)lr2 * BSTRIDE + kbase * 2;
#pragma unroll
            for (int n = 0; n < 8; n++) {
                const int lc = n * 8 + (lane & 3) * 2;
                uint32_t pk1, pk2;
                asm volatile("ld.shared.b32 %0, [%1];" : "=r"(pk1)
                             : "r"(b1 + (uint32_t)lc * 2));
                asm volatile("ld.shared.b32 %0, [%1];" : "=r"(pk2)
                             : "r"(b2 + (uint32_t)lc * 2));
                float* d = acc_s[mi][n];
                float p0 = ex2f(d[0] + __uint_as_float(pk1 << 16));
                float p1 = ex2f(d[1] + __uint_as_float(pk1 & 0xffff0000u));
                float p2 = ex2f(d[2] + __uint_as_float(pk2 << 16));
                float p3 = ex2f(d[3] + __uint_as_float(pk2 & 0xffff0000u));
                lsum[mi][0] += p0 + p1;
                lsum[mi][1] += p2 + p3;
                const int t = n >> 1, j = n & 1;
                pf[mi][t][2*j]     = pack_h2(p0, p1);   // rows r   (a0/a2)
                pf[mi][t][2*j + 1] = pack_h2(p2, p3);   // rows r+8 (a1/a3)
            }
        }

        // ---- O += P @ V (registers -> MMA, V via LDSM4T) ----
#pragma unroll
        for (int t = 0; t < 4; t++) {
            int rv = kbase + t * 16 + (sub >> 1) * 8 + lr;
#pragma unroll
            for (int dn = 0; dn < 4; dn++) {
                int cv = dn * 2 + (sub & 1);
                uint32_t off = sw128((uint32_t)(rv * 128 + cv * 16));
                uint32_t t0, t1, t2, t3;
                LDSM4T(t0, t1, t2, t3, bkv + OFF_V + off);
                uint32_t b0[2] = {t0, t2}, b1a[2] = {t1, t3};
#pragma unroll
                for (int mi = 0; mi < 2; mi++) {
                    MMA16816(acc_o[mi][2*dn],     pf[mi][t], b0);
                    MMA16816(acc_o[mi][2*dn + 1], pf[mi][t], b1a);
                }
            }
        }
        __syncthreads();
    }

    // ---- cross-pair reduction: ng=1 dumps O + lsum, ng=0 finalizes ----
    float* obuf = reinterpret_cast<float*>(sm + ASTG0);          // 16KB (64x64)
    float* sbuf = reinterpret_cast<float*>(sm + ASTG0 + 16384);  // 128 floats

#pragma unroll
    for (int mi = 0; mi < 2; mi++)
#pragma unroll
        for (int h = 0; h < 2; h++) {
            float v = lsum[mi][h];
            v += __shfl_xor_sync(0xffffffffu, v, 1);
            v += __shfl_xor_sync(0xffffffffu, v, 2);
            if ((lane & 3) == 0)
                sbuf[ng * 64 + m0w + mi * 16 + h * 8 + (lane >> 2)] = v;
        }

    if (ng == 1) {
#pragma unroll
        for (int mi = 0; mi < 2; mi++) {
            const int lr1 = m0w + mi * 16 + (lane >> 2);
            const int lr2 = lr1 + 8;
#pragma unroll
            for (int n = 0; n < 8; n++) {
                const int col = n * 8 + (lane & 3) * 2;
                float* d = acc_o[mi][n];
                float2 v1 = {d[0], d[1]}, v2 = {d[2], d[3]};
                *reinterpret_cast<float2*>(&obuf[lr1 * 64 + col]) = v1;
                *reinterpret_cast<float2*>(&obuf[lr2 * 64 + col]) = v2;
            }
        }
    }
    __syncthreads();

    if (ng == 0) {
#pragma unroll
        for (int mi = 0; mi < 2; mi++) {
            const int lr1 = m0w + mi * 16 + (lane >> 2);
            const int lr2 = lr1 + 8;
            const float i1 = 1.0f / (sbuf[lr1] + sbuf[64 + lr1]);
            const float i2 = 1.0f / (sbuf[lr2] + sbuf[64 + lr2]);
#pragma unroll
            for (int n = 0; n < 8; n++) {
                const int col = n * 8 + (lane & 3) * 2;
                float* d = acc_o[mi][n];
                float2 o1 = *reinterpret_cast<float2*>(&obuf[lr1 * 64 + col]);
                float2 o2 = *reinterpret_cast<float2*>(&obuf[lr2 * 64 + col]);
                size_t idx = (size_t)(q0 + lr1) * E + hoff + col;
                *reinterpret_cast<uint32_t*>(Cx + idx) =
                    pack_h2((d[0] + o1.x) * i1, (d[1] + o1.y) * i1);
                idx = (size_t)(q0 + lr2) * E + hoff + col;
                *reinterpret_cast<uint32_t*>(Cx + idx) =
                    pack_h2((d[2] + o2.x) * i2, (d[3] + o2.y) * i2);
            }
        }
    }
}

// ---------------- host side ----------------
extern "C" void kernel_launch(void* const* d_in, const int* in_sizes, int n_in,
                              void* d_out, int out_size)
{
    const float* values = (const float*)d_in[0];
    const float* keys   = (const float*)d_in[1];
    const float* query  = (const float*)d_in[2];
    const float* dist   = (const float*)d_in[3];
    const float* Wv     = (const float*)d_in[4];
    const float* Wk     = (const float*)d_in[5];
    const float* Wq     = (const float*)d_in[6];
    const float* Wo     = (const float*)d_in[7];
    const float* bo     = (const float*)d_in[8];
    float* out = (float*)d_out;

    __half *xq, *xk, *xv, *wq, *wk, *wv, *wo;
    __half *pq, *pk, *pv, *cx;
    __nv_bfloat16* biasbf;
    cudaGetSymbolAddress((void**)&xq, g_xq);
    cudaGetSymbolAddress((void**)&xk, g_xk);
    cudaGetSymbolAddress((void**)&xv, g_xv);
    cudaGetSymbolAddress((void**)&wq, g_wq);
    cudaGetSymbolAddress((void**)&wk, g_wk);
    cudaGetSymbolAddress((void**)&wv, g_wv);
    cudaGetSymbolAddress((void**)&wo, g_wo);
    cudaGetSymbolAddress((void**)&pq, g_pq);
    cudaGetSymbolAddress((void**)&pk, g_pk);
    cudaGetSymbolAddress((void**)&pv, g_pv);
    cudaGetSymbolAddress((void**)&cx, g_cx);
    cudaGetSymbolAddress((void**)&biasbf, g_biasbf);

    cudaFuncSetAttribute(gemm1_qkv, cudaFuncAttributeMaxDynamicSharedMemorySize, G1_SMEM);
    cudaFuncSetAttribute(gemm1_o,   cudaFuncAttributeMaxDynamicSharedMemorySize, G1_SMEM);
    cudaFuncSetAttribute(attn_tc,   cudaFuncAttributeMaxDynamicSharedMemorySize, ATTN_SMEM);

    // launches: 1 conv+bias, 2 qkv, 3 attn, 4 o
    const int nConv = (3 * LE + 4 * EE + L * L) / 4 / 256;
    conv_all<<<nConv, 256>>>(query, keys, values, Wq, Wk, Wv, Wo, dist,
                             xq, xk, xv, wq, wk, wv, wo, biasbf);

    dim3 gqkv(E / 128, L / 128, 3);   // 384 CTAs
    gemm1_qkv<<<gqkv, 128, G1_SMEM>>>(xq, wq, pq, xk, wk, pk, xv, wv, pv);

    attn_tc<<<dim3(L / 64, NH), 128, ATTN_SMEM>>>(pq, pk, pv, biasbf, cx);

    dim3 go(E / 128, L / 128);        // 128 CTAs
    gemm1_o<<<go, 128, G1_SMEM>>>(cx, wo, out, bo);
}

// round 17
// speedup vs baseline: 1.2589x; 1.0295x over previous
#include <cuda_runtime.h>
#include <cuda_fp16.h>
#include <cuda_bf16.h>
#include <cstdint>

// ---------------- problem constants ----------------
constexpr int L  = 2048;
constexpr int E  = 1024;
constexpr int NH = 16;
constexpr int HD = 64;
constexpr float KSCALE = 0.04508422002778011f;   // log2(e)/32

// ---------------- device scratch (all 1-term fp16) ----------------
__device__ __half g_xq[L * E], g_xk[L * E], g_xv[L * E];
__device__ __half g_wq[E * E], g_wk[E * E], g_wv[E * E], g_wo[E * E];
__device__ __half g_pq[L * E];                  // projected Q (scaled)
__device__ __half g_pk[L * E];                  // projected K
__device__ __half g_pv[L * E];                  // projected V
__device__ __half g_cx[L * E];                  // context
__device__ __nv_bfloat16 g_biasbf[(size_t)L * L];  // bias * log2e/32, bf16

// ---------------- helpers ----------------
__device__ __forceinline__ uint32_t s2u(const void* p) {
    uint32_t a;
    asm("{ .reg .u64 t; cvta.to.shared.u64 t, %1; cvt.u32.u64 %0, t; }"
        : "=r"(a) : "l"(p));
    return a;
}
__device__ __forceinline__ uint32_t sw128(uint32_t off) {
    return off ^ ((off >> 3) & 0x70);
}
__device__ __forceinline__ float ex2f(float x) {
    float r; asm("ex2.approx.f32 %0, %1;" : "=f"(r) : "f"(x)); return r;
}
__device__ __forceinline__ uint32_t pack_h2(float lo, float hi) {
    uint32_t r;
    asm("cvt.rn.f16x2.f32 %0, %1, %2;" : "=r"(r) : "f"(hi), "f"(lo));
    return r;
}
__device__ __forceinline__ uint32_t pack_bf2(float lo, float hi) {
    uint32_t r;
    asm("cvt.rn.bf16x2.f32 %0, %1, %2;" : "=r"(r) : "f"(hi), "f"(lo));
    return r;
}

#define CP_ASYNC16(dst, src) \
    asm volatile("cp.async.cg.shared.global [%0], [%1], 16;" :: "r"(dst), "l"(src))
#define CP_COMMIT() asm volatile("cp.async.commit_group;" ::: "memory")
#define CP_WAIT1()  asm volatile("cp.async.wait_group 1;" ::: "memory")
#define CP_WAIT0()  asm volatile("cp.async.wait_group 0;" ::: "memory")

#define LDSM4(r0, r1, r2, r3, a) \
    asm volatile("ldmatrix.sync.aligned.m8n8.x4.shared.b16 {%0,%1,%2,%3}, [%4];" \
        : "=r"(r0), "=r"(r1), "=r"(r2), "=r"(r3) : "r"(a))
#define LDSM4T(r0, r1, r2, r3, a) \
    asm volatile("ldmatrix.sync.aligned.m8n8.x4.trans.shared.b16 {%0,%1,%2,%3}, [%4];" \
        : "=r"(r0), "=r"(r1), "=r"(r2), "=r"(r3) : "r"(a))

#define MMA16816(d, a, b) \
    asm volatile("mma.sync.aligned.m16n8k16.row.col.f32.f16.f16.f32 " \
        "{%0,%1,%2,%3}, {%4,%5,%6,%7}, {%8,%9}, {%0,%1,%2,%3};" \
        : "+f"((d)[0]), "+f"((d)[1]), "+f"((d)[2]), "+f"((d)[3]) \
        : "r"((a)[0]), "r"((a)[1]), "r"((a)[2]), "r"((a)[3]), \
          "r"((b)[0]), "r"((b)[1]))

// cp.async one [128 x 64] f16 tile, 128 threads
__device__ __forceinline__ void cp_tile_h(uint32_t dst, const __half* src,
                                          int ld, int tid) {
#pragma unroll
    for (int i = 0; i < 8; i++) {
        int u   = i * 128 + tid;
        int row = u >> 3;
        int ch  = u & 7;
        uint32_t d = dst + sw128((uint32_t)(row * 128 + ch * 16));
        CP_ASYNC16(d, src + (size_t)row * ld + ch * 8);
    }
}

// cp.async one [64 x 64] f16 tile, 128 threads
__device__ __forceinline__ void cp_tile_q(uint32_t dst, const __half* src,
                                          int ld, int tid) {
#pragma unroll
    for (int i = 0; i < 4; i++) {
        int u   = i * 128 + tid;
        int row = u >> 3;
        int ch  = u & 7;
        uint32_t d = dst + sw128((uint32_t)(row * 128 + ch * 16));
        CP_ASYNC16(d, src + (size_t)row * ld + ch * 8);
    }
}

// cp.async bias slice [64 rows x 128 keys] bf16, row stride 272B (pad), 128 thr
constexpr uint32_t BSTRIDE = 272;
__device__ __forceinline__ void cp_bias(uint32_t dst,
                                        const __nv_bfloat16* src,   // row 0, key 0
                                        int tid) {
#pragma unroll
    for (int i = 0; i < 8; i++) {
        int u   = i * 128 + tid;
        int row = u >> 4;          // 0..63
        int ch  = u & 15;          // 16B chunk within 256B row
        uint32_t d = dst + row * BSTRIDE + ch * 16;
        CP_ASYNC16(d, src + (size_t)row * L + ch * 8);
    }
}

// ---------------- fused conversion + bias prep (single launch) ----------------
__device__ __forceinline__ void conv1_at(const float* s, __half* d, int i) {
    float4 v = *reinterpret_cast<const float4*>(s + i);
    uint2 o = { pack_h2(v.x, v.y), pack_h2(v.z, v.w) };
    *reinterpret_cast<uint2*>(d + i) = o;
}

constexpr int LE = L * E, EE = E * E;

__global__ void conv_all(const float* q, const float* k, const float* v,
                         const float* Wq, const float* Wk,
                         const float* Wv, const float* Wo,
                         const float* dist,
                         __half* xq, __half* xk, __half* xv,
                         __half* wq, __half* wk, __half* wv, __half* wo,
                         __nv_bfloat16* biasbf)
{
    int i = (blockIdx.x * blockDim.x + threadIdx.x) * 4;
    if (i < LE) { conv1_at(q, xq, i); return; }
    i -= LE;
    if (i < LE) { conv1_at(k, xk, i); return; }
    i -= LE;
    if (i < LE) { conv1_at(v, xv, i); return; }
    i -= LE;
    if (i < EE) { conv1_at(Wq, wq, i); return; }
    i -= EE;
    if (i < EE) { conv1_at(Wk, wk, i); return; }
    i -= EE;
    if (i < EE) { conv1_at(Wv, wv, i); return; }
    i -= EE;
    if (i < EE) { conv1_at(Wo, wo, i); return; }
    i -= EE;
    // bias table: bf16( log2e/32 * 1/(d+1) )
    float4 v4 = *reinterpret_cast<const float4*>(dist + i);
    float o0 = (v4.x == 0.f) ? 0.f : KSCALE / (v4.x + 1.f);
    float o1 = (v4.y == 0.f) ? 0.f : KSCALE / (v4.y + 1.f);
    float o2 = (v4.z == 0.f) ? 0.f : KSCALE / (v4.z + 1.f);
    float o3 = (v4.w == 0.f) ? 0.f : KSCALE / (v4.w + 1.f);
    uint2 o = { pack_bf2(o0, o1), pack_bf2(o2, o3) };
    *reinterpret_cast<uint2*>(biasbf + i) = o;
}

// ---------------- 1-term GEMM core ----------------
// 64x128 CTA tile, 128 threads (2x2 warps of 32x64), 3 CTAs/SM.
// smem per stage: A 8K + B 16K = 24K; double buffered = 48K.
constexpr int G1_SMEM = 49152;

template <typename EPI>
__device__ __forceinline__ void gemm1_body(const __half* A, const __half* B,
                                           int m0, int n0, EPI epi)
{
    extern __shared__ char sm[];
    const uint32_t sb = s2u(sm);
    const int tid  = threadIdx.x;
    const int wid  = tid >> 5;
    const int lane = tid & 31;
    const int m0w  = (wid >> 1) * 32;
    const int n0w  = (wid & 1) * 64;
    const int sub = lane >> 3, lr = lane & 7;
    const int K = E;

    float acc[2][8][4];
#pragma unroll
    for (int i = 0; i < 2; i++)
#pragma unroll
        for (int j = 0; j < 8; j++)
#pragma unroll
            for (int k = 0; k < 4; k++) acc[i][j][k] = 0.f;

    const int NC = K / 64;
    cp_tile_q(sb,        A + (size_t)m0 * K, K, tid);
    cp_tile_h(sb + 8192, B + (size_t)n0 * K, K, tid);
    CP_COMMIT();

    for (int kc = 0; kc < NC; kc++) {
        if (kc + 1 < NC) {
            uint32_t base = sb + ((kc + 1) & 1) * 24576;
            const int k0 = (kc + 1) * 64;
            cp_tile_q(base,        A + (size_t)m0 * K + k0, K, tid);
            cp_tile_h(base + 8192, B + (size_t)n0 * K + k0, K, tid);
            CP_COMMIT();
            CP_WAIT1();
        } else {
            CP_WAIT0();
        }
        __syncthreads();

        const uint32_t base = sb + (kc & 1) * 24576;
#pragma unroll
        for (int ks = 0; ks < 4; ks++) {
            const int ch = ks * 2 + (sub >> 1);
            uint32_t ah[2][4], bh[8][2];
#pragma unroll
            for (int mi = 0; mi < 2; mi++) {
                int r = m0w + mi * 16 + (sub & 1) * 8 + lr;
                uint32_t off = sw128((uint32_t)(r * 128 + ch * 16));
                LDSM4(ah[mi][0], ah[mi][1], ah[mi][2], ah[mi][3], base + off);
            }
#pragma unroll
            for (int ng = 0; ng < 4; ng++) {
                int r = n0w + ng * 16 + (sub & 1) * 8 + lr;
                uint32_t off = sw128((uint32_t)(r * 128 + ch * 16));
                uint32_t t0, t1, t2, t3;
                LDSM4(t0, t1, t2, t3, base + 8192 + off);
                bh[2*ng][0] = t0; bh[2*ng][1] = t2;
                bh[2*ng+1][0] = t1; bh[2*ng+1][1] = t3;
            }
#pragma unroll
            for (int mi = 0; mi < 2; mi++)
#pragma unroll
                for (int ni = 0; ni < 8; ni++)
                    MMA16816(acc[mi][ni], ah[mi], bh[ni]);
        }
        __syncthreads();
    }

#pragma unroll
    for (int mi = 0; mi < 2; mi++) {
        int r1 = m0 + m0w + mi * 16 + (lane >> 2);
#pragma unroll
        for (int ni = 0; ni < 8; ni++) {
            int col = n0 + n0w + ni * 8 + (lane & 3) * 2;
            epi(acc[mi][ni], r1, col);
        }
    }
}

__global__ void __launch_bounds__(128, 3)
gemm1_qkv(const __half* __restrict__ xq, const __half* __restrict__ wq,
          __half* __restrict__ pq,
          const __half* __restrict__ xk, const __half* __restrict__ wk,
          __half* __restrict__ pk,
          const __half* __restrict__ xv, const __half* __restrict__ wv,
          __half* __restrict__ pv)
{
    const __half* A = (blockIdx.z == 0) ? xq : (blockIdx.z == 1) ? xk : xv;
    const __half* B = (blockIdx.z == 0) ? wq : (blockIdx.z == 1) ? wk : wv;
    __half* C       = (blockIdx.z == 0) ? pq : (blockIdx.z == 1) ? pk : pv;
    const float oscale = (blockIdx.z == 0) ? KSCALE : 1.0f;
    const int m0 = blockIdx.y * 64, n0 = blockIdx.x * 128;

    gemm1_body(A, B, m0, n0,
        [&](float* d, int r1, int col) {
            *reinterpret_cast<uint32_t*>(C + (size_t)r1 * E + col) =
                pack_h2(d[0] * oscale, d[1] * oscale);
            *reinterpret_cast<uint32_t*>(C + (size_t)(r1 + 8) * E + col) =
                pack_h2(d[2] * oscale, d[3] * oscale);
        });
}

__global__ void __launch_bounds__(128, 3)
gemm1_o(const __half* __restrict__ cx, const __half* __restrict__ wo,
        float* __restrict__ out, const float* __restrict__ bvec)
{
    const int m0 = blockIdx.y * 64, n0 = blockIdx.x * 128;
    gemm1_body(cx, wo, m0, n0,
        [&](float* d, int r1, int col) {
            float2 bv = *reinterpret_cast<const float2*>(bvec + col);
            float2 o1 = {d[0] + bv.x, d[1] + bv.y};
            float2 o2 = {d[2] + bv.x, d[3] + bv.y};
            *reinterpret_cast<float2*>(out + (size_t)r1 * E + col) = o1;
            *reinterpret_cast<float2*>(out + (size_t)(r1 + 8) * E + col) = o2;
        });
}

// ---------------- attention (R16: register P + bias in cp.async pipe) --------
constexpr uint32_t AQ    = 0;
constexpr uint32_t ASTG0 = 8192;
constexpr uint32_t STG_SZ = 16384 + 16384 + 64 * BSTRIDE;   // 50176
constexpr uint32_t ASTG1 = ASTG0 + STG_SZ;                  // 58368
constexpr uint32_t OFF_V = 16384;
constexpr uint32_t OFF_B = 32768;
constexpr int ATTN_SMEM = (int)(ASTG1 + STG_SZ);            // 108544

__global__ void __launch_bounds__(128, 2)
attn_tc(const __half* __restrict__ Q,
        const __half* __restrict__ Kp,
        const __half* __restrict__ Vp,
        const __nv_bfloat16* __restrict__ biasbf,
        __half* __restrict__ Cx)
{
    extern __shared__ char sm[];
    const uint32_t sb = s2u(sm);
    const int tid  = threadIdx.x;
    const int wid  = tid >> 5;
    const int lane = tid & 31;
    const int mg   = wid >> 1;          // 0..1, rows mg*32
    const int ng   = wid & 1;           // 0..1, keys ng*64
    const int m0w  = mg * 32;
    const int kbase = ng * 64;
    const int q0   = blockIdx.x * 64;
    const int hoff = blockIdx.y * HD;
    const int sub = lane >> 3, lr = lane & 7;
    const __nv_bfloat16* brow0 = biasbf + (size_t)q0 * L;   // CTA's bias rows

    // prologue: Q group, then stage0 group (K,V,bias for tile 0)
    cp_tile_q(sb + AQ, Q + (size_t)q0 * E + hoff, E, tid);
    CP_COMMIT();
    cp_tile_h(sb + ASTG0,         Kp + hoff, E, tid);
    cp_tile_h(sb + ASTG0 + OFF_V, Vp + hoff, E, tid);
    cp_bias  (sb + ASTG0 + OFF_B, brow0, tid);
    CP_COMMIT();
    CP_WAIT1();            // Q group done
    __syncthreads();

    // Q fragments in registers: [ks][mi][4], rows m0w + mi*16
    uint32_t qf[4][2][4];
#pragma unroll
    for (int ks = 0; ks < 4; ks++) {
        const int ch = ks * 2 + (sub >> 1);
#pragma unroll
        for (int mi = 0; mi < 2; mi++) {
            int r = m0w + mi * 16 + (sub & 1) * 8 + lr;
            uint32_t off = sw128((uint32_t)(r * 128 + ch * 16));
            LDSM4(qf[ks][mi][0], qf[ks][mi][1], qf[ks][mi][2], qf[ks][mi][3],
                  sb + AQ + off);
        }
    }

    float acc_o[2][8][4];
#pragma unroll
    for (int i = 0; i < 2; i++)
#pragma unroll
        for (int j = 0; j < 8; j++)
#pragma unroll
            for (int k = 0; k < 4; k++) acc_o[i][j][k] = 0.f;
    float lsum[2][2];
    lsum[0][0] = lsum[0][1] = lsum[1][0] = lsum[1][1] = 0.f;

    for (int kt = 0; kt < L / 128; kt++) {
        const int kb = kt * 128;
        if (kt + 1 < L / 128) {
            uint32_t base = sb + (((kt + 1) & 1) ? ASTG1 : ASTG0);
            const size_t ro = (size_t)(kb + 128) * E + hoff;
            cp_tile_h(base,         Kp + ro, E, tid);
            cp_tile_h(base + OFF_V, Vp + ro, E, tid);
            cp_bias  (base + OFF_B, brow0 + kb + 128, tid);
            CP_COMMIT();
            CP_WAIT1();
        } else {
            CP_WAIT0();
        }
        __syncthreads();

        const uint32_t bkv = sb + ((kt & 1) ? ASTG1 : ASTG0);

        // ---- S = Q @ K^T over this warp's 64 keys ----
        float acc_s[2][8][4];
#pragma unroll
        for (int i = 0; i < 2; i++)
#pragma unroll
            for (int j = 0; j < 8; j++)
#pragma unroll
                for (int k = 0; k < 4; k++) acc_s[i][j][k] = 0.f;

#pragma unroll
        for (int ks = 0; ks < 4; ks++) {
            const int ch = ks * 2 + (sub >> 1);
            uint32_t bh[8][2];
#pragma unroll
            for (int kg = 0; kg < 4; kg++) {
                int r = kbase + kg * 16 + (sub & 1) * 8 + lr;
                uint32_t off = sw128((uint32_t)(r * 128 + ch * 16));
                uint32_t t0, t1, t2, t3;
                LDSM4(t0, t1, t2, t3, bkv + off);
                bh[2*kg][0] = t0; bh[2*kg][1] = t2;
                bh[2*kg+1][0] = t1; bh[2*kg+1][1] = t3;
            }
#pragma unroll
            for (int mi = 0; mi < 2; mi++)
#pragma unroll
                for (int n = 0; n < 8; n++)
                    MMA16816(acc_s[mi][n], qf[ks][mi], bh[n]);
        }

        // ---- p = ex2(S + bias[smem]) in registers; pack to PV A-frags ----
        uint32_t pf[2][4][4];
#pragma unroll
        for (int mi = 0; mi < 2; mi++) {
            const int lr1 = m0w + mi * 16 + (lane >> 2);   // local row 0..63
            const int lr2 = lr1 + 8;
            const uint32_t b1 = bkv + OFF_B + (uint32_t)lr1 * BSTRIDE + kbase * 2;
            const uint32_t b2 = bkv + OFF_B + (uint32_t)lr2 * BSTRIDE + kbase * 2;
#pragma unroll
            for (int n = 0; n < 8; n++) {
                const int lc = n * 8 + (lane & 3) * 2;
                uint32_t pk1, pk2;
                asm volatile("ld.shared.b32 %0, [%1];" : "=r"(pk1)
                             : "r"(b1 + (uint32_t)lc * 2));
                asm volatile("ld.shared.b32 %0, [%1];" : "=r"(pk2)
                             : "r"(b2 + (uint32_t)lc * 2));
                float* d = acc_s[mi][n];
                float p0 = ex2f(d[0] + __uint_as_float(pk1 << 16));
                float p1 = ex2f(d[1] + __uint_as_float(pk1 & 0xffff0000u));
                float p2 = ex2f(d[2] + __uint_as_float(pk2 << 16));
                float p3 = ex2f(d[3] + __uint_as_float(pk2 & 0xffff0000u));
                lsum[mi][0] += p0 + p1;
                lsum[mi][1] += p2 + p3;
                const int t = n >> 1, j = n & 1;
                pf[mi][t][2*j]     = pack_h2(p0, p1);   // rows r   (a0/a2)
                pf[mi][t][2*j + 1] = pack_h2(p2, p3);   // rows r+8 (a1/a3)
            }
        }

        // ---- O += P @ V (registers -> MMA, V via LDSM4T) ----
#pragma unroll
        for (int t = 0; t < 4; t++) {
            int rv = kbase + t * 16 + (sub >> 1) * 8 + lr;
#pragma unroll
            for (int dn = 0; dn < 4; dn++) {
                int cv = dn * 2 + (sub & 1);
                uint32_t off = sw128((uint32_t)(rv * 128 + cv * 16));
                uint32_t t0, t1, t2, t3;
                LDSM4T(t0, t1, t2, t3, bkv + OFF_V + off);
                uint32_t b0[2] = {t0, t2}, b1a[2] = {t1, t3};
#pragma unroll
                for (int mi = 0; mi < 2; mi++) {
                    MMA16816(acc_o[mi][2*dn],     pf[mi][t], b0);
                    MMA16816(acc_o[mi][2*dn + 1], pf[mi][t], b1a);
                }
            }
        }
        __syncthreads();
    }

    // ---- cross-pair reduction: ng=1 dumps O + lsum, ng=0 finalizes ----
    float* obuf = reinterpret_cast<float*>(sm + ASTG0);          // 16KB (64x64)
    float* sbuf = reinterpret_cast<float*>(sm + ASTG0 + 16384);  // 128 floats

#pragma unroll
    for (int mi = 0; mi < 2; mi++)
#pragma unroll
        for (int h = 0; h < 2; h++) {
            float v = lsum[mi][h];
            v += __shfl_xor_sync(0xffffffffu, v, 1);
            v += __shfl_xor_sync(0xffffffffu, v, 2);
            if ((lane & 3) == 0)
                sbuf[ng * 64 + m0w + mi * 16 + h * 8 + (lane >> 2)] = v;
        }

    if (ng == 1) {
#pragma unroll
        for (int mi = 0; mi < 2; mi++) {
            const int lr1 = m0w + mi * 16 + (lane >> 2);
            const int lr2 = lr1 + 8;
#pragma unroll
            for (int n = 0; n < 8; n++) {
                const int col = n * 8 + (lane & 3) * 2;
                float* d = acc_o[mi][n];
                float2 v1 = {d[0], d[1]}, v2 = {d[2], d[3]};
                *reinterpret_cast<float2*>(&obuf[lr1 * 64 + col]) = v1;
                *reinterpret_cast<float2*>(&obuf[lr2 * 64 + col]) = v2;
            }
        }
    }
    __syncthreads();

    if (ng == 0) {
#pragma unroll
        for (int mi = 0; mi < 2; mi++) {
            const int lr1 = m0w + mi * 16 + (lane >> 2);
            const int lr2 = lr1 + 8;
            const float i1 = 1.0f / (sbuf[lr1] + sbuf[64 + lr1]);
            const float i2 = 1.0f / (sbuf[lr2] + sbuf[64 + lr2]);
#pragma unroll
            for (int n = 0; n < 8; n++) {
                const int col = n * 8 + (lane & 3) * 2;
                float* d = acc_o[mi][n];
                float2 o1 = *reinterpret_cast<float2*>(&obuf[lr1 * 64 + col]);
                float2 o2 = *reinterpret_cast<float2*>(&obuf[lr2 * 64 + col]);
                size_t idx = (size_t)(q0 + lr1) * E + hoff + col;
                *reinterpret_cast<uint32_t*>(Cx + idx) =
                    pack_h2((d[0] + o1.x) * i1, (d[1] + o1.y) * i1);
                idx = (size_t)(q0 + lr2) * E + hoff + col;
                *reinterpret_cast<uint32_t*>(Cx + idx) =
                    pack_h2((d[2] + o2.x) * i2, (d[3] + o2.y) * i2);
            }
        }
    }
}

// ---------------- host side ----------------
extern "C" void kernel_launch(void* const* d_in, const int* in_sizes, int n_in,
                              void* d_out, int out_size)
{
    const float* values = (const float*)d_in[0];
    const float* keys   = (const float*)d_in[1];
    const float* query  = (const float*)d_in[2];
    const float* dist   = (const float*)d_in[3];
    const float* Wv     = (const float*)d_in[4];
    const float* Wk     = (const float*)d_in[5];
    const float* Wq     = (const float*)d_in[6];
    const float* Wo     = (const float*)d_in[7];
    const float* bo     = (const float*)d_in[8];
    float* out = (float*)d_out;

    __half *xq, *xk, *xv, *wq, *wk, *wv, *wo;
    __half *pq, *pk, *pv, *cx;
    __nv_bfloat16* biasbf;
    cudaGetSymbolAddress((void**)&xq, g_xq);
    cudaGetSymbolAddress((void**)&xk, g_xk);
    cudaGetSymbolAddress((void**)&xv, g_xv);
    cudaGetSymbolAddress((void**)&wq, g_wq);
    cudaGetSymbolAddress((void**)&wk, g_wk);
    cudaGetSymbolAddress((void**)&wv, g_wv);
    cudaGetSymbolAddress((void**)&wo, g_wo);
    cudaGetSymbolAddress((void**)&pq, g_pq);
    cudaGetSymbolAddress((void**)&pk, g_pk);
    cudaGetSymbolAddress((void**)&pv, g_pv);
    cudaGetSymbolAddress((void**)&cx, g_cx);
    cudaGetSymbolAddress((void**)&biasbf, g_biasbf);

    cudaFuncSetAttribute(gemm1_qkv, cudaFuncAttributeMaxDynamicSharedMemorySize, G1_SMEM);
    cudaFuncSetAttribute(gemm1_o,   cudaFuncAttributeMaxDynamicSharedMemorySize, G1_SMEM);
    cudaFuncSetAttribute(attn_tc,   cudaFuncAttributeMaxDynamicSharedMemorySize, ATTN_SMEM);

    // launches: 1 conv+bias, 2 qkv, 3 attn, 4 o
    const int nConv = (3 * LE + 4 * EE + L * L) / 4 / 256;
    conv_all<<<nConv, 256>>>(query, keys, values, Wq, Wk, Wv, Wo, dist,
                             xq, xk, xv, wq, wk, wv, wo, biasbf);

    dim3 gqkv(E / 128, L / 64, 3);    // (8, 32, 3) = 768 CTAs
    gemm1_qkv<<<gqkv, 128, G1_SMEM>>>(xq, wq, pq, xk, wk, pk, xv, wv, pv);

    attn_tc<<<dim3(L / 64, NH), 128, ATTN_SMEM>>>(pq, pk, pv, biasbf, cx);

    dim3 go(E / 128, L / 64);         // (8, 32) = 256 CTAs
    gemm1_o<<<go, 128, G1_SMEM>>>(cx, wo, out, bo);
}